// round 1
// baseline (speedup 1.0000x reference)
#include <cuda_runtime.h>
#include <cuda_bf16.h>
#include <math.h>

// Problem constants
#define BATCH 4
#define DIM   512
#define MLEN  4096          // 64*64 pixels == m
#define HEADS 8
#define HD    64            // DIM/HEADS
#define KCONV 4608          // 512*9

// ---------------- static scratch (no allocations allowed) ----------------
__device__ float g_kv   [BATCH * 2 * DIM * MLEN];   // k rows [0,512), v rows [512,1024)
__device__ float g_q1   [BATCH * DIM * MLEN];
__device__ float g_q    [BATCH * DIM * MLEN];
__device__ float g_part [BATCH * HEADS * 8 * HD * HD];
__device__ float g_attn [BATCH * HEADS * HD * HD];
__device__ float g_rq   [BATCH * DIM];
__device__ float g_rk   [BATCH * DIM];
__device__ float g_w2   [BATCH * DIM * DIM];

// ---------------- generic tiled SGEMM: C[b] = A[b] (MxK, row-major) * B[b] (KxN) ----
// BM=BN=128, BK=8, 256 threads, 8x8 per thread. M%128==0, N%128==0, K%8==0.
__global__ __launch_bounds__(256, 2)
void sgemm_kernel(const float* __restrict__ A, long lA,
                  const float* __restrict__ B, long lB,
                  float* __restrict__ C, long lC,
                  int M, int N, int K)
{
    A += (long)blockIdx.z * lA;
    B += (long)blockIdx.z * lB;
    C += (long)blockIdx.z * lC;
    const int bm = blockIdx.y * 128;
    const int bn = blockIdx.x * 128;

    __shared__ float As[8][128];
    __shared__ float Bs[8][128];

    const int tid  = threadIdx.x;
    const int arow = tid >> 1;          // 0..127
    const int acol = (tid & 1) * 4;     // 0,4
    const int brow = tid >> 5;          // 0..7
    const int bcol = (tid & 31) * 4;    // 0..124
    const int tx   = tid & 15;
    const int ty   = tid >> 4;

    float acc[8][8];
#pragma unroll
    for (int i = 0; i < 8; i++)
#pragma unroll
        for (int j = 0; j < 8; j++) acc[i][j] = 0.f;

    for (int k0 = 0; k0 < K; k0 += 8) {
        float4 a = *(const float4*)(A + (long)(bm + arow) * K + k0 + acol);
        As[acol + 0][arow] = a.x;
        As[acol + 1][arow] = a.y;
        As[acol + 2][arow] = a.z;
        As[acol + 3][arow] = a.w;
        *(float4*)(&Bs[brow][bcol]) =
            *(const float4*)(B + (long)(k0 + brow) * N + bn + bcol);
        __syncthreads();
#pragma unroll
        for (int k = 0; k < 8; k++) {
            float ra[8], rb[8];
#pragma unroll
            for (int i = 0; i < 8; i++) ra[i] = As[k][ty * 8 + i];
#pragma unroll
            for (int j = 0; j < 8; j++) rb[j] = Bs[k][tx * 8 + j];
#pragma unroll
            for (int i = 0; i < 8; i++)
#pragma unroll
                for (int j = 0; j < 8; j++) acc[i][j] += ra[i] * rb[j];
        }
        __syncthreads();
    }
#pragma unroll
    for (int i = 0; i < 8; i++) {
        float* cp = C + (long)(bm + ty * 8 + i) * N + bn + tx * 8;
        *(float4*)(cp)     = make_float4(acc[i][0], acc[i][1], acc[i][2], acc[i][3]);
        *(float4*)(cp + 4) = make_float4(acc[i][4], acc[i][5], acc[i][6], acc[i][7]);
    }
}

// ---------------- implicit-GEMM 3x3 dense conv -----------------------------
// q[b] (512 x 4096) = w_dw (512 x 4608, row-major = [o][i*9+ky*3+kx]) * im2col(q1[b])
__global__ __launch_bounds__(256, 2)
void conv_gemm_kernel(const float* __restrict__ W,
                      const float* __restrict__ Q1,
                      float* __restrict__ Qo)
{
    const int bb = blockIdx.z;
    const float* B0 = Q1 + (long)bb * DIM * MLEN;
    float* C = Qo + (long)bb * DIM * MLEN;
    const int bm = blockIdx.y * 128;
    const int bn = blockIdx.x * 128;

    __shared__ float As[8][128];
    __shared__ float Bs[8][128];

    const int tid  = threadIdx.x;
    const int arow = tid >> 1;
    const int acol = (tid & 1) * 4;
    const int brow = tid >> 5;
    const int bcol = (tid & 31) * 4;
    const int tx   = tid & 15;
    const int ty   = tid >> 4;

    const int n  = bn + bcol;      // pixel index; 4 consecutive stay in one image row
    const int h  = n >> 6;
    const int w0 = n & 63;

    float acc[8][8];
#pragma unroll
    for (int i = 0; i < 8; i++)
#pragma unroll
        for (int j = 0; j < 8; j++) acc[i][j] = 0.f;

    for (int k0 = 0; k0 < KCONV; k0 += 8) {
        float4 a = *(const float4*)(W + (long)(bm + arow) * KCONV + k0 + acol);
        As[acol + 0][arow] = a.x;
        As[acol + 1][arow] = a.y;
        As[acol + 2][arow] = a.z;
        As[acol + 3][arow] = a.w;

        // im2col gather for this B row
        const int k  = k0 + brow;
        const int ic = k / 9;
        const int t  = k - ic * 9;
        const int dy = t / 3 - 1;
        const int dx = t - (t / 3) * 3 - 1;
        const int hh = h + dy;
        const bool hok = (hh >= 0) & (hh < 64);
        const float* src = B0 + ((long)ic * 64 + hh) * 64;
#pragma unroll
        for (int j = 0; j < 4; j++) {
            const int ww = w0 + dx + j;
            Bs[brow][bcol + j] =
                (hok && ww >= 0 && ww < 64) ? src[ww] : 0.f;
        }
        __syncthreads();
#pragma unroll
        for (int k2 = 0; k2 < 8; k2++) {
            float ra[8], rb[8];
#pragma unroll
            for (int i = 0; i < 8; i++) ra[i] = As[k2][ty * 8 + i];
#pragma unroll
            for (int j = 0; j < 8; j++) rb[j] = Bs[k2][tx * 8 + j];
#pragma unroll
            for (int i = 0; i < 8; i++)
#pragma unroll
                for (int j = 0; j < 8; j++) acc[i][j] += ra[i] * rb[j];
        }
        __syncthreads();
    }
#pragma unroll
    for (int i = 0; i < 8; i++) {
        float* cp = C + (long)(bm + ty * 8 + i) * MLEN + bn + tx * 8;
        *(float4*)(cp)     = make_float4(acc[i][0], acc[i][1], acc[i][2], acc[i][3]);
        *(float4*)(cp + 4) = make_float4(acc[i][4], acc[i][5], acc[i][6], acc[i][7]);
    }
}

// ---------------- reciprocal row L2 norms for q and k -----------------------
__global__ void norms_kernel(const float* __restrict__ Q,
                             const float* __restrict__ KV,
                             float* __restrict__ rq, float* __restrict__ rk)
{
    const int idx = blockIdx.x;          // 0..4095
    const int b = idx >> 10;
    const int r = idx & 1023;
    const float* p;
    float* outp;
    if (r < DIM) { p = Q  + ((long)b * DIM + r) * MLEN;          outp = rq + b * DIM + r; }
    else         { p = KV + ((long)b * 2 * DIM + (r - DIM)) * MLEN; outp = rk + b * DIM + (r - DIM); }

    const int tid = threadIdx.x;
    float ss = 0.f;
    for (int i = tid; i < MLEN; i += 256) { float v = p[i]; ss += v * v; }
#pragma unroll
    for (int o = 16; o; o >>= 1) ss += __shfl_xor_sync(~0u, ss, o);
    __shared__ float red[8];
    if ((tid & 31) == 0) red[tid >> 5] = ss;
    __syncthreads();
    if (tid < 8) {
        ss = red[tid];
#pragma unroll
        for (int o = 4; o; o >>= 1) ss += __shfl_xor_sync(0xffu, ss, o);
        if (tid == 0) *outp = 1.f / fmaxf(sqrtf(ss), 1e-12f);
    }
}

// ---------------- attention logits, m split 8 ways ------------------------
__global__ __launch_bounds__(256)
void attn_partial_kernel(const float* __restrict__ Q,
                         const float* __restrict__ KV,
                         float* __restrict__ part)
{
    const int mc = blockIdx.x;   // 0..7
    const int h  = blockIdx.y;
    const int b  = blockIdx.z;
    const float* Qp = Q  + ((long)(b * DIM + h * HD)) * MLEN + mc * 512;
    const float* Kp = KV + ((long)(b * 2 * DIM + h * HD)) * MLEN + mc * 512;

    __shared__ float sq[32][64];
    __shared__ float sk[32][64];

    const int tid  = threadIdx.x;
    const int row  = tid >> 2;          // 0..63
    const int mg   = (tid & 3) * 8;     // 0,8,16,24
    const int tx   = tid & 15;
    const int ty   = tid >> 4;

    float acc[4][4];
#pragma unroll
    for (int i = 0; i < 4; i++)
#pragma unroll
        for (int j = 0; j < 4; j++) acc[i][j] = 0.f;

    for (int mt = 0; mt < 512; mt += 32) {
        float4 a0 = *(const float4*)(Qp + (long)row * MLEN + mt + mg);
        float4 a1 = *(const float4*)(Qp + (long)row * MLEN + mt + mg + 4);
        sq[mg + 0][row] = a0.x; sq[mg + 1][row] = a0.y;
        sq[mg + 2][row] = a0.z; sq[mg + 3][row] = a0.w;
        sq[mg + 4][row] = a1.x; sq[mg + 5][row] = a1.y;
        sq[mg + 6][row] = a1.z; sq[mg + 7][row] = a1.w;
        float4 b0 = *(const float4*)(Kp + (long)row * MLEN + mt + mg);
        float4 b1 = *(const float4*)(Kp + (long)row * MLEN + mt + mg + 4);
        sk[mg + 0][row] = b0.x; sk[mg + 1][row] = b0.y;
        sk[mg + 2][row] = b0.z; sk[mg + 3][row] = b0.w;
        sk[mg + 4][row] = b1.x; sk[mg + 5][row] = b1.y;
        sk[mg + 6][row] = b1.z; sk[mg + 7][row] = b1.w;
        __syncthreads();
#pragma unroll
        for (int mm = 0; mm < 32; mm++) {
            float ra[4], rb[4];
#pragma unroll
            for (int i = 0; i < 4; i++) ra[i] = sq[mm][ty * 4 + i];
#pragma unroll
            for (int j = 0; j < 4; j++) rb[j] = sk[mm][tx * 4 + j];
#pragma unroll
            for (int i = 0; i < 4; i++)
#pragma unroll
                for (int j = 0; j < 4; j++) acc[i][j] += ra[i] * rb[j];
        }
        __syncthreads();
    }
    float* pp = part + ((((long)(b * HEADS + h)) * 8 + mc) * HD + ty * 4) * HD + tx * 4;
#pragma unroll
    for (int i = 0; i < 4; i++)
#pragma unroll
        for (int j = 0; j < 4; j++) pp[i * HD + j] = acc[i][j];
}

// ---------------- reduce partials, apply norms+temperature, softmax over d --
__global__ void softmax_kernel(const float* __restrict__ part,
                               const float* __restrict__ rq,
                               const float* __restrict__ rk,
                               const float* __restrict__ temp,
                               float* __restrict__ attn)
{
    const int row = blockIdx.x;          // 0..2047
    const int b = row >> 9;
    const int h = (row >> 6) & 7;
    const int c = row & 63;
    const int lane = threadIdx.x;        // 32 threads

    const float tq = rq[b * DIM + h * HD + c] * temp[h];
    float v[2];
#pragma unroll
    for (int j = 0; j < 2; j++) {
        const int d = lane + 32 * j;
        const long base = (((long)(b * HEADS + h)) * 8) * (HD * HD) + c * HD + d;
        float s = 0.f;
#pragma unroll
        for (int mc = 0; mc < 8; mc++) s += part[base + (long)mc * (HD * HD)];
        v[j] = s * tq * rk[b * DIM + h * HD + d];
    }
    float mx = fmaxf(v[0], v[1]);
#pragma unroll
    for (int o = 16; o; o >>= 1) mx = fmaxf(mx, __shfl_xor_sync(~0u, mx, o));
    const float e0 = expf(v[0] - mx);
    const float e1 = expf(v[1] - mx);
    float s = e0 + e1;
#pragma unroll
    for (int o = 16; o; o >>= 1) s += __shfl_xor_sync(~0u, s, o);
    const float inv = 1.f / s;
    float* ap = attn + (((long)(b * HEADS + h)) * HD + c) * HD;
    ap[lane]      = e0 * inv;
    ap[lane + 32] = e1 * inv;
}

// ---------------- W2[b] = w_out @ blockdiag(attn[b]) -----------------------
__global__ void w2_kernel(const float* __restrict__ w_out,
                          const float* __restrict__ attn,
                          float* __restrict__ W2)
{
    const int b = blockIdx.z;
    const int h = blockIdx.y;
    const int tid = threadIdx.x;
    __shared__ float sa[HD * HD];
    const float* ap = attn + ((long)(b * HEADS + h)) * HD * HD;
    for (int i = tid; i < HD * HD; i += 256) sa[i] = ap[i];
    __syncthreads();
    const int o = blockIdx.x * 4 + (tid >> 6);
    const int d = tid & 63;
    const float* wrow = w_out + (long)o * DIM + h * HD;
    float acc = 0.f;
#pragma unroll
    for (int c = 0; c < HD; c++) acc += wrow[c] * sa[c * HD + d];
    W2[((long)b * DIM + o) * DIM + h * HD + d] = acc;
}

// ---------------- launcher --------------------------------------------------
extern "C" void kernel_launch(void* const* d_in, const int* in_sizes, int n_in,
                              void* d_out, int out_size)
{
    const float* x    = (const float*)d_in[0];   // (4,512,4096)
    const float* y    = (const float*)d_in[1];   // (4,512,64,64)
    const float* temp = (const float*)d_in[2];   // (8,1,1)
    const float* wkv  = (const float*)d_in[3];   // (1024,512)
    const float* wq   = (const float*)d_in[4];   // (512,512)
    const float* wdw  = (const float*)d_in[5];   // (512,512,3,3)
    const float* wout = (const float*)d_in[6];   // (512,512)
    float* out = (float*)d_out;                  // (4,512,4096)

    float *kv, *q1, *q, *part, *attn, *rq, *rk, *w2;
    cudaGetSymbolAddress((void**)&kv,   g_kv);
    cudaGetSymbolAddress((void**)&q1,   g_q1);
    cudaGetSymbolAddress((void**)&q,    g_q);
    cudaGetSymbolAddress((void**)&part, g_part);
    cudaGetSymbolAddress((void**)&attn, g_attn);
    cudaGetSymbolAddress((void**)&rq,   g_rq);
    cudaGetSymbolAddress((void**)&rk,   g_rk);
    cudaGetSymbolAddress((void**)&w2,   g_w2);

    // 1) kv = w_kv @ x   (1024 x 4096, K=512, per batch)
    sgemm_kernel<<<dim3(32, 8, BATCH), 256>>>(
        wkv, 0L, x, (long)DIM * MLEN, kv, (long)2 * DIM * MLEN,
        2 * DIM, MLEN, DIM);

    // 2) q1 = w_q @ y    (512 x 4096)
    sgemm_kernel<<<dim3(32, 4, BATCH), 256>>>(
        wq, 0L, y, (long)DIM * MLEN, q1, (long)DIM * MLEN,
        DIM, MLEN, DIM);

    // 3) q = conv3x3(q1) via implicit GEMM  (interp with L==M is identity)
    conv_gemm_kernel<<<dim3(32, 4, BATCH), 256>>>(wdw, q1, q);

    // 4) reciprocal L2 norms of q rows and k rows
    norms_kernel<<<BATCH * 1024, 256>>>(q, kv, rq, rk);

    // 5) attention logits (m split 8 ways)
    attn_partial_kernel<<<dim3(8, HEADS, BATCH), 256>>>(q, kv, part);

    // 6) reduce + scale + softmax
    softmax_kernel<<<BATCH * HEADS * HD, 32>>>(part, rq, rk, temp, attn);

    // 7) W2 = w_out @ blockdiag(attn)
    w2_kernel<<<dim3(128, HEADS, BATCH), 256>>>(wout, attn, w2);

    // 8) out = W2 @ v
    sgemm_kernel<<<dim3(32, 4, BATCH), 256>>>(
        w2, (long)DIM * DIM, kv + (long)DIM * MLEN, (long)2 * DIM * MLEN,
        out, (long)DIM * MLEN, DIM, MLEN, DIM);
}

// round 2
// speedup vs baseline: 2.6826x; 2.6826x over previous
#include <cuda_runtime.h>
#include <math.h>
#include <stdint.h>

#define BATCH 4
#define DIM   512
#define MLEN  4096
#define HEADS 8
#define HD    64
#define KCONV 4608

// ---------------- static scratch ----------------
__device__ float g_kv  [BATCH * 2 * DIM * MLEN];
__device__ float g_q1  [BATCH * DIM * MLEN];
__device__ float g_q   [BATCH * DIM * MLEN];
__device__ float g_part[BATCH * HEADS * 8 * HD * HD];
__device__ float g_attn[BATCH * HEADS * HD * HD];
__device__ float g_rq  [BATCH * DIM];
__device__ float g_rk  [BATCH * DIM];
__device__ float g_w2  [BATCH * DIM * DIM];

// ---------------- tf32 helpers ----------------
__device__ __forceinline__ uint32_t f2tf32(float x) {
    uint32_t r;
    asm("cvt.rna.tf32.f32 %0, %1;" : "=r"(r) : "f"(x));
    return r;
}

__device__ __forceinline__ void mma8(float& c0, float& c1, float& c2, float& c3,
                                     uint32_t a0, uint32_t a1, uint32_t a2, uint32_t a3,
                                     uint32_t b0, uint32_t b1) {
    asm volatile(
        "mma.sync.aligned.m16n8k8.row.col.f32.tf32.tf32.f32 "
        "{%0,%1,%2,%3}, {%4,%5,%6,%7}, {%8,%9}, {%0,%1,%2,%3};"
        : "+f"(c0), "+f"(c1), "+f"(c2), "+f"(c3)
        : "r"(a0), "r"(a1), "r"(a2), "r"(a3), "r"(b0), "r"(b1));
}

#define SSTR 136   // smem row stride (floats); 136 % 32 == 8 -> conflict-free frags

// ---------------- unified tf32 tensor GEMM ----------------
// C[b] (MxN) = A[b] (MxK row-major) * B[b] (KxN row-major or conv-im2col)
// Block tile 128x128, BK=16, 256 threads, warp tile 64x32.
template <int CONV>
__global__ __launch_bounds__(256)
void tgemm(const float* __restrict__ A, long lA,
           const float* __restrict__ B, long lB,
           float* __restrict__ C, long lC,
           int M, int N, int K)
{
    A += (long)blockIdx.z * lA;
    B += (long)blockIdx.z * lB;
    C += (long)blockIdx.z * lC;
    const int bm = blockIdx.y * 128;
    const int bn = blockIdx.x * 128;

    __shared__ __align__(16) uint32_t As[2][16 * SSTR];
    __shared__ __align__(16) uint32_t Bs[2][16 * SSTR];

    const int tid  = threadIdx.x;
    const int lane = tid & 31;
    const int warp = tid >> 5;
    const int wm   = (warp >> 2) * 64;   // warp row offset in tile
    const int wn   = (warp & 3) * 32;    // warp col offset in tile
    const int g    = lane >> 2;          // groupID
    const int t    = lane & 3;           // threadID_in_group

    float acc[4][4][4];
#pragma unroll
    for (int i = 0; i < 4; i++)
#pragma unroll
        for (int j = 0; j < 4; j++)
#pragma unroll
            for (int r = 0; r < 4; r++) acc[i][j][r] = 0.f;

    float4 aP[2];
    float4 bP[2];
    float  bPc[8];

    const int T = K >> 4;

    // ---- prologue: global load tile 0 ----
#pragma unroll
    for (int i = 0; i < 2; i++) {
        int idx = tid + i * 256;
        aP[i] = *(const float4*)(A + (long)(bm + (idx >> 2)) * K + (idx & 3) * 4);
    }
    if (CONV) {
#pragma unroll
        for (int i = 0; i < 8; i++) {
            int e = tid + i * 256;
            int kr = e >> 7, j = e & 127;
            int k = kr;
            int ic = k / 9, r = k - ic * 9;
            int dy = r / 3 - 1, dx = r - (r / 3) * 3 - 1;
            int n = bn + j, h = n >> 6, w = n & 63;
            int hh = h + dy, ww = w + dx;
            bPc[i] = (hh >= 0 && hh < 64 && ww >= 0 && ww < 64)
                         ? B[(ic * 64 + hh) * 64 + ww] : 0.f;
        }
    } else {
#pragma unroll
        for (int i = 0; i < 2; i++) {
            int idx = tid + i * 256;
            bP[i] = *(const float4*)(B + (long)(idx >> 5) * N + bn + (idx & 31) * 4);
        }
    }
    // store tile 0 to smem buf 0
#pragma unroll
    for (int i = 0; i < 2; i++) {
        int idx = tid + i * 256;
        int row = idx >> 2, kc = (idx & 3) * 4;
        As[0][(kc + 0) * SSTR + row] = f2tf32(aP[i].x);
        As[0][(kc + 1) * SSTR + row] = f2tf32(aP[i].y);
        As[0][(kc + 2) * SSTR + row] = f2tf32(aP[i].z);
        As[0][(kc + 3) * SSTR + row] = f2tf32(aP[i].w);
        if (!CONV) {
            int kr = idx >> 5, nc = (idx & 31) * 4;
            uint4 v = make_uint4(f2tf32(bP[i].x), f2tf32(bP[i].y),
                                 f2tf32(bP[i].z), f2tf32(bP[i].w));
            *(uint4*)&Bs[0][kr * SSTR + nc] = v;
        }
    }
    if (CONV) {
#pragma unroll
        for (int i = 0; i < 8; i++) {
            int e = tid + i * 256;
            Bs[0][(e >> 7) * SSTR + (e & 127)] = f2tf32(bPc[i]);
        }
    }
    __syncthreads();

    for (int tt = 0; tt < T; ++tt) {
        const int buf = tt & 1;
        const int k0n = (tt + 1) << 4;

        // ---- prefetch next tile ----
        if (tt + 1 < T) {
#pragma unroll
            for (int i = 0; i < 2; i++) {
                int idx = tid + i * 256;
                aP[i] = *(const float4*)(A + (long)(bm + (idx >> 2)) * K + k0n + (idx & 3) * 4);
            }
            if (CONV) {
#pragma unroll
                for (int i = 0; i < 8; i++) {
                    int e = tid + i * 256;
                    int kr = e >> 7, j = e & 127;
                    int k = k0n + kr;
                    int ic = k / 9, r = k - ic * 9;
                    int dy = r / 3 - 1, dx = r - (r / 3) * 3 - 1;
                    int n = bn + j, h = n >> 6, w = n & 63;
                    int hh = h + dy, ww = w + dx;
                    bPc[i] = (hh >= 0 && hh < 64 && ww >= 0 && ww < 64)
                                 ? B[(ic * 64 + hh) * 64 + ww] : 0.f;
                }
            } else {
#pragma unroll
                for (int i = 0; i < 2; i++) {
                    int idx = tid + i * 256;
                    bP[i] = *(const float4*)(B + (long)(k0n + (idx >> 5)) * N + bn + (idx & 31) * 4);
                }
            }
        }

        // ---- compute on buf ----
#pragma unroll
        for (int k8 = 0; k8 < 2; k8++) {
            const uint32_t* a0r = &As[buf][(k8 * 8 + t) * SSTR];
            const uint32_t* a1r = &As[buf][(k8 * 8 + t + 4) * SSTR];
            const uint32_t* b0r = &Bs[buf][(k8 * 8 + t) * SSTR];
            const uint32_t* b1r = &Bs[buf][(k8 * 8 + t + 4) * SSTR];
            uint32_t af[4][4], bf[4][2];
#pragma unroll
            for (int mi = 0; mi < 4; mi++) {
                int m0 = wm + mi * 16 + g;
                af[mi][0] = a0r[m0];
                af[mi][1] = a0r[m0 + 8];
                af[mi][2] = a1r[m0];
                af[mi][3] = a1r[m0 + 8];
            }
#pragma unroll
            for (int ni = 0; ni < 4; ni++) {
                int n0 = wn + ni * 8 + g;
                bf[ni][0] = b0r[n0];
                bf[ni][1] = b1r[n0];
            }
#pragma unroll
            for (int mi = 0; mi < 4; mi++)
#pragma unroll
                for (int ni = 0; ni < 4; ni++)
                    mma8(acc[mi][ni][0], acc[mi][ni][1], acc[mi][ni][2], acc[mi][ni][3],
                         af[mi][0], af[mi][1], af[mi][2], af[mi][3],
                         bf[ni][0], bf[ni][1]);
        }

        // ---- store next tile to buf^1 ----
        if (tt + 1 < T) {
            const int nb = buf ^ 1;
#pragma unroll
            for (int i = 0; i < 2; i++) {
                int idx = tid + i * 256;
                int row = idx >> 2, kc = (idx & 3) * 4;
                As[nb][(kc + 0) * SSTR + row] = f2tf32(aP[i].x);
                As[nb][(kc + 1) * SSTR + row] = f2tf32(aP[i].y);
                As[nb][(kc + 2) * SSTR + row] = f2tf32(aP[i].z);
                As[nb][(kc + 3) * SSTR + row] = f2tf32(aP[i].w);
                if (!CONV) {
                    int kr = idx >> 5, nc = (idx & 31) * 4;
                    uint4 v = make_uint4(f2tf32(bP[i].x), f2tf32(bP[i].y),
                                         f2tf32(bP[i].z), f2tf32(bP[i].w));
                    *(uint4*)&Bs[nb][kr * SSTR + nc] = v;
                }
            }
            if (CONV) {
#pragma unroll
                for (int i = 0; i < 8; i++) {
                    int e = tid + i * 256;
                    Bs[nb][(e >> 7) * SSTR + (e & 127)] = f2tf32(bPc[i]);
                }
            }
        }
        __syncthreads();
    }

    // ---- epilogue ----
#pragma unroll
    for (int mi = 0; mi < 4; mi++) {
        int row0 = bm + wm + mi * 16 + g;
#pragma unroll
        for (int ni = 0; ni < 4; ni++) {
            int col = bn + wn + ni * 8 + 2 * t;
            *(float2*)(C + (long)row0 * N + col) =
                make_float2(acc[mi][ni][0], acc[mi][ni][1]);
            *(float2*)(C + (long)(row0 + 8) * N + col) =
                make_float2(acc[mi][ni][2], acc[mi][ni][3]);
        }
    }
}

// ---------------- reciprocal row L2 norms ----------------
__global__ void norms_kernel(const float* __restrict__ Q,
                             const float* __restrict__ KV,
                             float* __restrict__ rq, float* __restrict__ rk)
{
    const int idx = blockIdx.x;
    const int b = idx >> 10;
    const int r = idx & 1023;
    const float* p;
    float* outp;
    if (r < DIM) { p = Q  + ((long)b * DIM + r) * MLEN;             outp = rq + b * DIM + r; }
    else         { p = KV + ((long)b * 2 * DIM + (r - DIM)) * MLEN; outp = rk + b * DIM + (r - DIM); }

    const int tid = threadIdx.x;
    float ss = 0.f;
    for (int i = tid; i < MLEN; i += 256) { float v = p[i]; ss += v * v; }
#pragma unroll
    for (int o = 16; o; o >>= 1) ss += __shfl_xor_sync(~0u, ss, o);
    __shared__ float red[8];
    if ((tid & 31) == 0) red[tid >> 5] = ss;
    __syncthreads();
    if (tid < 8) {
        ss = red[tid];
#pragma unroll
        for (int o = 4; o; o >>= 1) ss += __shfl_xor_sync(0xffu, ss, o);
        if (tid == 0) *outp = 1.f / fmaxf(sqrtf(ss), 1e-12f);
    }
}

// ---------------- attention logits (m split 8 ways) ----------------
__global__ __launch_bounds__(256)
void attn_partial_kernel(const float* __restrict__ Q,
                         const float* __restrict__ KV,
                         float* __restrict__ part)
{
    const int mc = blockIdx.x;
    const int h  = blockIdx.y;
    const int b  = blockIdx.z;
    const float* Qp = Q  + ((long)(b * DIM + h * HD)) * MLEN + mc * 512;
    const float* Kp = KV + ((long)(b * 2 * DIM + h * HD)) * MLEN + mc * 512;

    __shared__ float sq[32][64];
    __shared__ float sk[32][64];

    const int tid = threadIdx.x;
    const int row = tid >> 2;
    const int mg  = (tid & 3) * 8;
    const int tx  = tid & 15;
    const int ty  = tid >> 4;

    float acc[4][4];
#pragma unroll
    for (int i = 0; i < 4; i++)
#pragma unroll
        for (int j = 0; j < 4; j++) acc[i][j] = 0.f;

    for (int mt = 0; mt < 512; mt += 32) {
        float4 a0 = *(const float4*)(Qp + (long)row * MLEN + mt + mg);
        float4 a1 = *(const float4*)(Qp + (long)row * MLEN + mt + mg + 4);
        sq[mg + 0][row] = a0.x; sq[mg + 1][row] = a0.y;
        sq[mg + 2][row] = a0.z; sq[mg + 3][row] = a0.w;
        sq[mg + 4][row] = a1.x; sq[mg + 5][row] = a1.y;
        sq[mg + 6][row] = a1.z; sq[mg + 7][row] = a1.w;
        float4 b0 = *(const float4*)(Kp + (long)row * MLEN + mt + mg);
        float4 b1 = *(const float4*)(Kp + (long)row * MLEN + mt + mg + 4);
        sk[mg + 0][row] = b0.x; sk[mg + 1][row] = b0.y;
        sk[mg + 2][row] = b0.z; sk[mg + 3][row] = b0.w;
        sk[mg + 4][row] = b1.x; sk[mg + 5][row] = b1.y;
        sk[mg + 6][row] = b1.z; sk[mg + 7][row] = b1.w;
        __syncthreads();
#pragma unroll
        for (int mm = 0; mm < 32; mm++) {
            float ra[4], rb[4];
#pragma unroll
            for (int i = 0; i < 4; i++) ra[i] = sq[mm][ty * 4 + i];
#pragma unroll
            for (int j = 0; j < 4; j++) rb[j] = sk[mm][tx * 4 + j];
#pragma unroll
            for (int i = 0; i < 4; i++)
#pragma unroll
                for (int j = 0; j < 4; j++) acc[i][j] += ra[i] * rb[j];
        }
        __syncthreads();
    }
    float* pp = part + ((((long)(b * HEADS + h)) * 8 + mc) * HD + ty * 4) * HD + tx * 4;
#pragma unroll
    for (int i = 0; i < 4; i++)
#pragma unroll
        for (int j = 0; j < 4; j++) pp[i * HD + j] = acc[i][j];
}

// ---------------- softmax over d ----------------
__global__ void softmax_kernel(const float* __restrict__ part,
                               const float* __restrict__ rq,
                               const float* __restrict__ rk,
                               const float* __restrict__ temp,
                               float* __restrict__ attn)
{
    const int row = blockIdx.x;
    const int b = row >> 9;
    const int h = (row >> 6) & 7;
    const int c = row & 63;
    const int lane = threadIdx.x;

    const float tq = rq[b * DIM + h * HD + c] * temp[h];
    float v[2];
#pragma unroll
    for (int j = 0; j < 2; j++) {
        const int d = lane + 32 * j;
        const long base = (((long)(b * HEADS + h)) * 8) * (HD * HD) + c * HD + d;
        float s = 0.f;
#pragma unroll
        for (int mc = 0; mc < 8; mc++) s += part[base + (long)mc * (HD * HD)];
        v[j] = s * tq * rk[b * DIM + h * HD + d];
    }
    float mx = fmaxf(v[0], v[1]);
#pragma unroll
    for (int o = 16; o; o >>= 1) mx = fmaxf(mx, __shfl_xor_sync(~0u, mx, o));
    const float e0 = expf(v[0] - mx);
    const float e1 = expf(v[1] - mx);
    float s = e0 + e1;
#pragma unroll
    for (int o = 16; o; o >>= 1) s += __shfl_xor_sync(~0u, s, o);
    const float inv = 1.f / s;
    float* ap = attn + (((long)(b * HEADS + h)) * HD + c) * HD;
    ap[lane]      = e0 * inv;
    ap[lane + 32] = e1 * inv;
}

// ---------------- W2 = w_out @ blockdiag(attn) ----------------
__global__ void w2_kernel(const float* __restrict__ w_out,
                          const float* __restrict__ attn,
                          float* __restrict__ W2)
{
    const int b = blockIdx.z;
    const int h = blockIdx.y;
    const int tid = threadIdx.x;
    __shared__ float sa[HD * HD];
    const float* ap = attn + ((long)(b * HEADS + h)) * HD * HD;
    for (int i = tid; i < HD * HD; i += 256) sa[i] = ap[i];
    __syncthreads();
    const int o = blockIdx.x * 4 + (tid >> 6);
    const int d = tid & 63;
    const float* wrow = w_out + (long)o * DIM + h * HD;
    float acc = 0.f;
#pragma unroll
    for (int c = 0; c < HD; c++) acc += wrow[c] * sa[c * HD + d];
    W2[((long)b * DIM + o) * DIM + h * HD + d] = acc;
}

// ---------------- launcher ----------------
extern "C" void kernel_launch(void* const* d_in, const int* in_sizes, int n_in,
                              void* d_out, int out_size)
{
    const float* x    = (const float*)d_in[0];
    const float* y    = (const float*)d_in[1];
    const float* temp = (const float*)d_in[2];
    const float* wkv  = (const float*)d_in[3];
    const float* wq   = (const float*)d_in[4];
    const float* wdw  = (const float*)d_in[5];
    const float* wout = (const float*)d_in[6];
    float* out = (float*)d_out;

    float *kv, *q1, *q, *part, *attn, *rq, *rk, *w2;
    cudaGetSymbolAddress((void**)&kv,   g_kv);
    cudaGetSymbolAddress((void**)&q1,   g_q1);
    cudaGetSymbolAddress((void**)&q,    g_q);
    cudaGetSymbolAddress((void**)&part, g_part);
    cudaGetSymbolAddress((void**)&attn, g_attn);
    cudaGetSymbolAddress((void**)&rq,   g_rq);
    cudaGetSymbolAddress((void**)&rk,   g_rk);
    cudaGetSymbolAddress((void**)&w2,   g_w2);

    // 1) kv = w_kv @ x   (1024 x 4096, K=512)
    tgemm<0><<<dim3(32, 8, BATCH), 256>>>(
        wkv, 0L, x, (long)DIM * MLEN, kv, (long)2 * DIM * MLEN,
        2 * DIM, MLEN, DIM);

    // 2) q1 = w_q @ y    (512 x 4096, K=512)
    tgemm<0><<<dim3(32, 4, BATCH), 256>>>(
        wq, 0L, y, (long)DIM * MLEN, q1, (long)DIM * MLEN,
        DIM, MLEN, DIM);

    // 3) q = conv3x3(q1) via implicit GEMM (K=4608); interp L==M is identity
    tgemm<1><<<dim3(32, 4, BATCH), 256>>>(
        wdw, 0L, q1, (long)DIM * MLEN, q, (long)DIM * MLEN,
        DIM, MLEN, KCONV);

    // 4) reciprocal L2 norms
    norms_kernel<<<BATCH * 1024, 256>>>(q, kv, rq, rk);

    // 5) attention logits
    attn_partial_kernel<<<dim3(8, HEADS, BATCH), 256>>>(q, kv, part);

    // 6) reduce + scale + softmax
    softmax_kernel<<<BATCH * HEADS * HD, 32>>>(part, rq, rk, temp, attn);

    // 7) W2 = w_out @ blockdiag(attn)
    w2_kernel<<<dim3(128, HEADS, BATCH), 256>>>(wout, attn, w2);

    // 8) out = W2 @ v
    tgemm<0><<<dim3(32, 4, BATCH), 256>>>(
        w2, (long)DIM * DIM, kv + (long)DIM * MLEN, (long)2 * DIM * MLEN,
        out, (long)DIM * MLEN, DIM, MLEN, DIM);
}

// round 3
// speedup vs baseline: 2.9494x; 1.0995x over previous
#include <cuda_runtime.h>
#include <math.h>
#include <stdint.h>

#define BATCH 4
#define DIM   512
#define MLEN  4096
#define HEADS 8
#define HD    64
#define KCONV 4608

#define STAGES 3
#define TILEK  16
#define SSTR   136                       // smem row stride in floats
#define ASTG   (TILEK * SSTR)            // floats per stage (one operand)
#define SMEMB  (STAGES * 2 * ASTG * 4)   // dynamic smem bytes = 52224

// ---------------- static scratch ----------------
__device__ float g_kv  [BATCH * 2 * DIM * MLEN];   // k rows [0,512), v rows [512,1024)
__device__ float g_q   [BATCH * DIM * MLEN];
__device__ float g_part[BATCH * HEADS * 8 * HD * HD];
__device__ float g_nsq [BATCH * HEADS * 8 * 2 * HD];
__device__ float g_attn[BATCH * HEADS * HD * HD];
__device__ float g_w2T [BATCH * DIM * DIM];
__device__ float g_wkvT[DIM * 2 * DIM];            // [c][o] 512x1024
__device__ float g_wqR [DIM * DIM];                // rounded wq
__device__ float g_wdwTr[9 * DIM * DIM];           // [r][o][o2]
__device__ float g_wc  [KCONV * DIM];              // WcT [c*9+r][o2]

// ---------------- helpers ----------------
__device__ __forceinline__ uint32_t f2tf32(float x) {
    uint32_t r;
    asm("cvt.rna.tf32.f32 %0, %1;" : "=r"(r) : "f"(x));
    return r;
}
__device__ __forceinline__ float rndf(float x) { return __uint_as_float(f2tf32(x)); }

__device__ __forceinline__ void mma8(float& c0, float& c1, float& c2, float& c3,
                                     uint32_t a0, uint32_t a1, uint32_t a2, uint32_t a3,
                                     uint32_t b0, uint32_t b1) {
    asm volatile(
        "mma.sync.aligned.m16n8k8.row.col.f32.tf32.tf32.f32 "
        "{%0,%1,%2,%3}, {%4,%5,%6,%7}, {%8,%9}, {%0,%1,%2,%3};"
        : "+f"(c0), "+f"(c1), "+f"(c2), "+f"(c3)
        : "r"(a0), "r"(a1), "r"(a2), "r"(a3), "r"(b0), "r"(b1));
}
__device__ __forceinline__ void cpa16(uint32_t d, const void* s) {
    asm volatile("cp.async.cg.shared.global [%0], [%1], 16;" :: "r"(d), "l"(s));
}
__device__ __forceinline__ void cpa4z(uint32_t d, const void* s, int sz) {
    asm volatile("cp.async.ca.shared.global [%0], [%1], 4, %2;" :: "r"(d), "l"(s), "r"(sz));
}
#define CP_COMMIT() asm volatile("cp.async.commit_group;")
#define CP_WAIT1()  asm volatile("cp.async.wait_group 1;")

// ---------------- unified tf32 GEMM with cp.async pipeline ----------------
// C[z] (MxN) = Ahat[z] (MxK) * B[z] (KxN), with Ahat supplied TRANSPOSED:
// AT is [K][M] row-major (weights pre-rounded to tf32).
// CONV: B is im2col(y[z]) with k = c*9 + r.  CVTB: round B frags at use.
template <int CONV, int CVTB>
__global__ __launch_bounds__(256)
void tgemm(const float* __restrict__ AT, long lA,
           const float* __restrict__ B, long lB,
           float* __restrict__ C, long lC, int ldC,
           int M, int N, int K, int roundC)
{
    extern __shared__ float sm[];
    AT += (long)blockIdx.z * lA;
    B  += (long)blockIdx.z * lB;
    C  += (long)blockIdx.z * lC;
    const int bm = blockIdx.y * 128;
    const int bn = blockIdx.x * 128;

    const int tid  = threadIdx.x;
    const int lane = tid & 31, warp = tid >> 5;
    const int wm = (warp >> 2) * 64, wn = (warp & 3) * 32;
    const int g = lane >> 2, t = lane & 3;

    float* As = sm;
    float* Bs = sm + STAGES * ASTG;
    const uint32_t aBase = (uint32_t)__cvta_generic_to_shared(As);
    const uint32_t bBase = (uint32_t)__cvta_generic_to_shared(Bs);

    // A / dense-B load coords
    const int lrow = tid >> 5;          // 0..7 (+8 for second)
    const int lcol = (tid & 31) * 4;

    // conv loader state
    int cIc = 0, cR = 0, cKrow = 0, cJ0 = 0, cH = 0, cW0 = 0;
    if (CONV) {
        cKrow = tid >> 4;               // 0..15
        cJ0   = (tid & 15) * 8;
        const int n0 = bn + cJ0;
        cH  = n0 >> 6;
        cW0 = n0 & 63;
        cIc = cKrow >= 9 ? 1 : 0;
        cR  = cKrow - 9 * cIc;
    }

    float acc[4][4][4];
#pragma unroll
    for (int i = 0; i < 4; i++)
#pragma unroll
        for (int j = 0; j < 4; j++)
#pragma unroll
            for (int r = 0; r < 4; r++) acc[i][j][r] = 0.f;

    const int T = K >> 4;

    auto load_stage = [&](int s, int k0) {
        // A tile: AT rows k0..k0+15, cols bm..bm+127
        const uint32_t aDst = aBase + (uint32_t)(s * ASTG + lrow * SSTR + lcol) * 4u;
        const float* aSrc = AT + (long)(k0 + lrow) * M + bm + lcol;
        cpa16(aDst, aSrc);
        cpa16(aDst + 8u * SSTR * 4u, aSrc + 8L * M);
        if (!CONV) {
            const uint32_t bDst = bBase + (uint32_t)(s * ASTG + lrow * SSTR + lcol) * 4u;
            const float* bSrc = B + (long)(k0 + lrow) * N + bn + lcol;
            cpa16(bDst, bSrc);
            cpa16(bDst + 8u * SSTR * 4u, bSrc + 8L * N);
        } else {
            const int dyr = (cR * 11) >> 5;       // cR/3
            const int dy = dyr - 1;
            const int dx = cR - 3 * dyr - 1;
            const int hh = cH + dy;
            const bool hok = (unsigned)hh < 64u;
            const float* rowp = B + ((long)cIc * 64 + hh) * 64;
            uint32_t dst = bBase + (uint32_t)(s * ASTG + cKrow * SSTR + cJ0) * 4u;
#pragma unroll
            for (int u = 0; u < 8; u++) {
                const int ww = cW0 + dx + u;
                const bool ok = hok && ((unsigned)ww < 64u);
                cpa4z(dst + 4u * u, ok ? (rowp + ww) : B, ok ? 4 : 0);
            }
            // advance (ic, r) by k += 16
            cR += 7; cIc += 1;
            if (cR >= 9) { cR -= 9; cIc += 1; }
        }
    };

    // prologue: stages 0,1
    load_stage(0, 0);  CP_COMMIT();
    load_stage(1, 16); CP_COMMIT();

    for (int tt = 0; tt < T; tt++) {
        CP_WAIT1();
        __syncthreads();
        if (tt + 2 < T) load_stage((tt + 2) % STAGES, (tt + 2) * TILEK);
        CP_COMMIT();

        const float* As_ = As + (tt % STAGES) * ASTG;
        const float* Bs_ = Bs + (tt % STAGES) * ASTG;
#pragma unroll
        for (int k8 = 0; k8 < 2; k8++) {
            const float* a0 = As_ + (k8 * 8 + t) * SSTR;
            const float* a1 = a0 + 4 * SSTR;
            const float* b0 = Bs_ + (k8 * 8 + t) * SSTR;
            const float* b1 = b0 + 4 * SSTR;
            uint32_t af[4][4], bf[4][2];
#pragma unroll
            for (int mi = 0; mi < 4; mi++) {
                const int m0 = wm + mi * 16 + g;
                af[mi][0] = __float_as_uint(a0[m0]);
                af[mi][1] = __float_as_uint(a0[m0 + 8]);
                af[mi][2] = __float_as_uint(a1[m0]);
                af[mi][3] = __float_as_uint(a1[m0 + 8]);
            }
#pragma unroll
            for (int ni = 0; ni < 4; ni++) {
                const int n0 = wn + ni * 8 + g;
                const float x0 = b0[n0], x1 = b1[n0];
                bf[ni][0] = CVTB ? f2tf32(x0) : __float_as_uint(x0);
                bf[ni][1] = CVTB ? f2tf32(x1) : __float_as_uint(x1);
            }
#pragma unroll
            for (int mi = 0; mi < 4; mi++)
#pragma unroll
                for (int ni = 0; ni < 4; ni++)
                    mma8(acc[mi][ni][0], acc[mi][ni][1], acc[mi][ni][2], acc[mi][ni][3],
                         af[mi][0], af[mi][1], af[mi][2], af[mi][3],
                         bf[ni][0], bf[ni][1]);
        }
    }

    const bool rnd = (roundC == 1) || (roundC == 2 && bm >= 512);
#pragma unroll
    for (int mi = 0; mi < 4; mi++) {
        const int row0 = bm + wm + mi * 16 + g;
#pragma unroll
        for (int ni = 0; ni < 4; ni++) {
            const int col = bn + wn + ni * 8 + 2 * t;
            float v0 = acc[mi][ni][0], v1 = acc[mi][ni][1];
            float v2 = acc[mi][ni][2], v3 = acc[mi][ni][3];
            if (rnd) { v0 = rndf(v0); v1 = rndf(v1); v2 = rndf(v2); v3 = rndf(v3); }
            *(float2*)(C + (long)row0 * ldC + col)       = make_float2(v0, v1);
            *(float2*)(C + (long)(row0 + 8) * ldC + col) = make_float2(v2, v3);
        }
    }
}

// ---------------- prep kernels (weights -> rounded / transposed) ----------
__global__ void prep_wq(const float* __restrict__ wq, float* __restrict__ wqR) {
    const int i = blockIdx.x * blockDim.x + threadIdx.x;
    if (i < DIM * DIM) wqR[i] = rndf(wq[i]);
}
__global__ void prep_wkvT(const float* __restrict__ wkv, float* __restrict__ wkvT) {
    __shared__ float tile[32][33];
    const int o0 = blockIdx.x * 32, c0 = blockIdx.y * 32;
    const int tx = threadIdx.x & 31, ty = threadIdx.x >> 5;
#pragma unroll
    for (int k = 0; k < 32; k += 8)
        tile[ty + k][tx] = wkv[(long)(o0 + ty + k) * DIM + c0 + tx];
    __syncthreads();
#pragma unroll
    for (int k = 0; k < 32; k += 8)
        wkvT[(long)(c0 + ty + k) * (2 * DIM) + o0 + tx] = rndf(tile[tx][ty + k]);
}
__global__ void prep_wdw(const float* __restrict__ wdw, float* __restrict__ wdwTr) {
    __shared__ float s[32][288];
    const int o20 = blockIdx.x * 32, o0 = blockIdx.y * 32;
    for (int idx = threadIdx.x; idx < 32 * 288; idx += 256) {
        const int seg = idx / 288, off = idx - seg * 288;
        s[seg][off] = wdw[((long)(o20 + seg) * DIM + o0) * 9 + off];
    }
    __syncthreads();
    for (int idx = threadIdx.x; idx < 9 * 32 * 32; idx += 256) {
        const int r = idx >> 10, ol = (idx >> 5) & 31, o2l = idx & 31;
        wdwTr[(long)r * (DIM * DIM) + (long)(o0 + ol) * DIM + o20 + o2l] =
            rndf(s[o2l][ol * 9 + r]);
    }
}

// ---------------- attention logits (m split 8 ways) + fused sumsq ---------
__global__ __launch_bounds__(256)
void attn_partial_kernel(const float* __restrict__ Q,
                         const float* __restrict__ KV,
                         float* __restrict__ part,
                         float* __restrict__ nsq)
{
    const int mc = blockIdx.x;
    const int h  = blockIdx.y;
    const int b  = blockIdx.z;
    const float* Qp = Q  + ((long)(b * DIM + h * HD)) * MLEN + mc * 512;
    const float* Kp = KV + ((long)(b * 2 * DIM + h * HD)) * MLEN + mc * 512;

    __shared__ float sq[32][64];
    __shared__ float sk[32][64];

    const int tid = threadIdx.x;
    const int row = tid >> 2;
    const int mg  = (tid & 3) * 8;
    const int tx  = tid & 15;
    const int ty  = tid >> 4;

    float acc[4][4];
#pragma unroll
    for (int i = 0; i < 4; i++)
#pragma unroll
        for (int j = 0; j < 4; j++) acc[i][j] = 0.f;

    float ssq = 0.f, ssk = 0.f;

    for (int mt = 0; mt < 512; mt += 32) {
        float4 a0 = *(const float4*)(Qp + (long)row * MLEN + mt + mg);
        float4 a1 = *(const float4*)(Qp + (long)row * MLEN + mt + mg + 4);
        sq[mg + 0][row] = a0.x; sq[mg + 1][row] = a0.y;
        sq[mg + 2][row] = a0.z; sq[mg + 3][row] = a0.w;
        sq[mg + 4][row] = a1.x; sq[mg + 5][row] = a1.y;
        sq[mg + 6][row] = a1.z; sq[mg + 7][row] = a1.w;
        ssq += a0.x*a0.x + a0.y*a0.y + a0.z*a0.z + a0.w*a0.w
             + a1.x*a1.x + a1.y*a1.y + a1.z*a1.z + a1.w*a1.w;
        float4 b0 = *(const float4*)(Kp + (long)row * MLEN + mt + mg);
        float4 b1 = *(const float4*)(Kp + (long)row * MLEN + mt + mg + 4);
        sk[mg + 0][row] = b0.x; sk[mg + 1][row] = b0.y;
        sk[mg + 2][row] = b0.z; sk[mg + 3][row] = b0.w;
        sk[mg + 4][row] = b1.x; sk[mg + 5][row] = b1.y;
        sk[mg + 6][row] = b1.z; sk[mg + 7][row] = b1.w;
        ssk += b0.x*b0.x + b0.y*b0.y + b0.z*b0.z + b0.w*b0.w
             + b1.x*b1.x + b1.y*b1.y + b1.z*b1.z + b1.w*b1.w;
        __syncthreads();
#pragma unroll
        for (int mm = 0; mm < 32; mm++) {
            float ra[4], rb[4];
#pragma unroll
            for (int i = 0; i < 4; i++) ra[i] = sq[mm][ty * 4 + i];
#pragma unroll
            for (int j = 0; j < 4; j++) rb[j] = sk[mm][tx * 4 + j];
#pragma unroll
            for (int i = 0; i < 4; i++)
#pragma unroll
                for (int j = 0; j < 4; j++) acc[i][j] += ra[i] * rb[j];
        }
        __syncthreads();
    }
    // reduce sumsq across the 4 loader threads of each row (lane bits 0,1)
    ssq += __shfl_xor_sync(~0u, ssq, 1); ssq += __shfl_xor_sync(~0u, ssq, 2);
    ssk += __shfl_xor_sync(~0u, ssk, 1); ssk += __shfl_xor_sync(~0u, ssk, 2);
    if ((tid & 3) == 0) {
        const long nb = (((long)(b * HEADS + h)) * 8 + mc) * 2 * HD;
        nsq[nb + row]      = ssq;
        nsq[nb + HD + row] = ssk;
    }
    float* pp = part + ((((long)(b * HEADS + h)) * 8 + mc) * HD + ty * 4) * HD + tx * 4;
#pragma unroll
    for (int i = 0; i < 4; i++)
#pragma unroll
        for (int j = 0; j < 4; j++) pp[i * HD + j] = acc[i][j];
}

// ---------------- reduce partials + norms + temperature + softmax ---------
__global__ void softmax_kernel(const float* __restrict__ part,
                               const float* __restrict__ nsq,
                               const float* __restrict__ temp,
                               float* __restrict__ attn)
{
    const int row = blockIdx.x;          // 0..2047
    const int b = row >> 9;
    const int h = (row >> 6) & 7;
    const int c = row & 63;
    const int lane = threadIdx.x;        // 32

    const long nb = ((long)(b * HEADS + h)) * 8 * 2 * HD;
    float sqs = 0.f, sk0 = 0.f, sk1 = 0.f;
#pragma unroll
    for (int mc = 0; mc < 8; mc++) {
        sqs += nsq[nb + mc * 2 * HD + c];
        sk0 += nsq[nb + mc * 2 * HD + HD + lane];
        sk1 += nsq[nb + mc * 2 * HD + HD + lane + 32];
    }
    const float rq  = 1.f / fmaxf(sqrtf(sqs), 1e-12f);
    const float rk0 = 1.f / fmaxf(sqrtf(sk0), 1e-12f);
    const float rk1 = 1.f / fmaxf(sqrtf(sk1), 1e-12f);
    const float tq = rq * temp[h];

    float v[2];
    {
        const long base = (((long)(b * HEADS + h)) * 8) * (HD * HD) + c * HD;
        float s0 = 0.f, s1 = 0.f;
#pragma unroll
        for (int mc = 0; mc < 8; mc++) {
            s0 += part[base + (long)mc * (HD * HD) + lane];
            s1 += part[base + (long)mc * (HD * HD) + lane + 32];
        }
        v[0] = s0 * tq * rk0;
        v[1] = s1 * tq * rk1;
    }
    float mx = fmaxf(v[0], v[1]);
#pragma unroll
    for (int o = 16; o; o >>= 1) mx = fmaxf(mx, __shfl_xor_sync(~0u, mx, o));
    const float e0 = expf(v[0] - mx);
    const float e1 = expf(v[1] - mx);
    float s = e0 + e1;
#pragma unroll
    for (int o = 16; o; o >>= 1) s += __shfl_xor_sync(~0u, s, o);
    const float inv = 1.f / s;
    float* ap = attn + (((long)(b * HEADS + h)) * HD + c) * HD;
    ap[lane]      = e0 * inv;
    ap[lane + 32] = e1 * inv;
}

// ---------------- W2T[k][o] = (w_out @ blockdiag(attn))^T, tf32-rounded ----
__global__ void w2_kernel(const float* __restrict__ w_out,
                          const float* __restrict__ attn,
                          float* __restrict__ W2T)
{
    const int b = blockIdx.z;
    const int h = blockIdx.y;
    const int tid = threadIdx.x;
    __shared__ float sa[HD * HD];
    __shared__ float sa2[4][HD];
    const float* ap = attn + ((long)(b * HEADS + h)) * HD * HD;
    for (int i = tid; i < HD * HD; i += 256) sa[i] = ap[i];
    __syncthreads();
    const int o = blockIdx.x * 4 + (tid >> 6);
    const int d = tid & 63;
    const float* wrow = w_out + (long)o * DIM + h * HD;
    float acc = 0.f;
#pragma unroll
    for (int c = 0; c < HD; c++) acc += wrow[c] * sa[c * HD + d];
    sa2[tid >> 6][d] = acc;
    __syncthreads();
    if (tid < 64) {
        float4 vv = make_float4(rndf(sa2[0][tid]), rndf(sa2[1][tid]),
                                rndf(sa2[2][tid]), rndf(sa2[3][tid]));
        *(float4*)&W2T[((long)b * DIM + h * HD + tid) * DIM + blockIdx.x * 4] = vv;
    }
}

// ---------------- launcher ----------------
extern "C" void kernel_launch(void* const* d_in, const int* in_sizes, int n_in,
                              void* d_out, int out_size)
{
    const float* x    = (const float*)d_in[0];
    const float* y    = (const float*)d_in[1];
    const float* temp = (const float*)d_in[2];
    const float* wkv  = (const float*)d_in[3];
    const float* wq   = (const float*)d_in[4];
    const float* wdw  = (const float*)d_in[5];
    const float* wout = (const float*)d_in[6];
    float* out = (float*)d_out;

    float *kv, *q, *part, *nsq, *attn, *w2T, *wkvT, *wqR, *wdwTr, *wc;
    cudaGetSymbolAddress((void**)&kv,    g_kv);
    cudaGetSymbolAddress((void**)&q,     g_q);
    cudaGetSymbolAddress((void**)&part,  g_part);
    cudaGetSymbolAddress((void**)&nsq,   g_nsq);
    cudaGetSymbolAddress((void**)&attn,  g_attn);
    cudaGetSymbolAddress((void**)&w2T,   g_w2T);
    cudaGetSymbolAddress((void**)&wkvT,  g_wkvT);
    cudaGetSymbolAddress((void**)&wqR,   g_wqR);
    cudaGetSymbolAddress((void**)&wdwTr, g_wdwTr);
    cudaGetSymbolAddress((void**)&wc,    g_wc);

    cudaFuncSetAttribute(tgemm<0,0>, cudaFuncAttributeMaxDynamicSharedMemorySize, SMEMB);
    cudaFuncSetAttribute(tgemm<0,1>, cudaFuncAttributeMaxDynamicSharedMemorySize, SMEMB);
    cudaFuncSetAttribute(tgemm<1,1>, cudaFuncAttributeMaxDynamicSharedMemorySize, SMEMB);

    // 0) weight prep (round to tf32, transpose)
    prep_wq  <<<512, 512>>>(wq, wqR);
    prep_wkvT<<<dim3(32, 16), 256>>>(wkv, wkvT);
    prep_wdw <<<dim3(16, 16), 256>>>(wdw, wdwTr);

    // 1) WcT[c*9+r][o2] = sum_o wq[o][c] * wdw[o2][o][r]   (9 GEMMs 512^3)
    tgemm<0,0><<<dim3(4, 4, 9), 256, SMEMB>>>(
        wqR, 0L, wdwTr, (long)DIM * DIM, wc, 512L, KCONV,
        DIM, DIM, DIM, 1);

    // 2) kv = w_kv @ x   (1024 x 4096, K=512); round v half
    tgemm<0,1><<<dim3(32, 8, BATCH), 256, SMEMB>>>(
        wkvT, 0L, x, (long)DIM * MLEN, kv, (long)2 * DIM * MLEN, MLEN,
        2 * DIM, MLEN, DIM, 2);

    // 3) q = Wc (*) im2col(y)   (512 x 4096, K=4608) — q1 GEMM fused away
    tgemm<1,1><<<dim3(32, 4, BATCH), 256, SMEMB>>>(
        wc, 0L, y, (long)DIM * MLEN, q, (long)DIM * MLEN, MLEN,
        DIM, MLEN, KCONV, 0);

    // 4) attention logits + fused row sumsq
    attn_partial_kernel<<<dim3(8, HEADS, BATCH), 256>>>(q, kv, part, nsq);

    // 5) reduce + norms + temperature + softmax
    softmax_kernel<<<BATCH * HEADS * HD, 32>>>(part, nsq, temp, attn);

    // 6) W2T = (w_out @ blockdiag(attn))^T, rounded
    w2_kernel<<<dim3(128, HEADS, BATCH), 256>>>(wout, attn, w2T);

    // 7) out = W2 @ v
    tgemm<0,0><<<dim3(32, 4, BATCH), 256, SMEMB>>>(
        w2T, (long)DIM * DIM, kv + (long)DIM * MLEN, (long)2 * DIM * MLEN,
        out, (long)DIM * MLEN, MLEN,
        DIM, MLEN, DIM, 0);
}

// round 4
// speedup vs baseline: 2.9558x; 1.0022x over previous
#include <cuda_runtime.h>
#include <math.h>
#include <stdint.h>

#define BATCH 4
#define DIM   512
#define MLEN  4096
#define HEADS 8
#define HD    64
#define KCONV 4608

#define STAGES 3
#define TILEK  16
#define SSTR   136                       // smem row stride in floats
#define ASTG   (TILEK * SSTR)            // floats per stage (one operand)
#define SMEMB  (STAGES * 2 * ASTG * 4)   // dynamic smem bytes = 52224

// ---------------- static scratch ----------------
__device__ float g_kv  [BATCH * 2 * DIM * MLEN];   // k rows [0,512), v rows [512,1024)
__device__ float g_q   [BATCH * DIM * MLEN];
__device__ float g_part[BATCH * HEADS * 8 * HD * HD];
__device__ float g_nsq [BATCH * HEADS * 8 * 2 * HD];
__device__ float g_attn[BATCH * HEADS * HD * HD];
__device__ float g_w2T [BATCH * DIM * DIM];
__device__ float g_wkvT[DIM * 2 * DIM];            // [c][o] 512x1024
__device__ float g_wqR [DIM * DIM];                // rounded wq
__device__ float g_wdwTr[9 * DIM * DIM];           // [r][o][o2]
__device__ float g_wc  [KCONV * DIM];              // WcT [c*9+r][o2]

// ---------------- helpers ----------------
__device__ __forceinline__ uint32_t f2tf32(float x) {
    uint32_t r;
    asm("cvt.rna.tf32.f32 %0, %1;" : "=r"(r) : "f"(x));
    return r;
}
__device__ __forceinline__ float rndf(float x) { return __uint_as_float(f2tf32(x)); }

__device__ __forceinline__ void mma8(float& c0, float& c1, float& c2, float& c3,
                                     uint32_t a0, uint32_t a1, uint32_t a2, uint32_t a3,
                                     uint32_t b0, uint32_t b1) {
    asm volatile(
        "mma.sync.aligned.m16n8k8.row.col.f32.tf32.tf32.f32 "
        "{%0,%1,%2,%3}, {%4,%5,%6,%7}, {%8,%9}, {%0,%1,%2,%3};"
        : "+f"(c0), "+f"(c1), "+f"(c2), "+f"(c3)
        : "r"(a0), "r"(a1), "r"(a2), "r"(a3), "r"(b0), "r"(b1));
}
__device__ __forceinline__ void cpa16(uint32_t d, const void* s) {
    asm volatile("cp.async.cg.shared.global [%0], [%1], 16;" :: "r"(d), "l"(s));
}
__device__ __forceinline__ void cpa4z(uint32_t d, const void* s, int sz) {
    asm volatile("cp.async.ca.shared.global [%0], [%1], 4, %2;" :: "r"(d), "l"(s), "r"(sz));
}
#define CP_COMMIT() asm volatile("cp.async.commit_group;")
#define CP_WAIT1()  asm volatile("cp.async.wait_group 1;")

// ---------------- unified tf32 GEMM with cp.async pipeline ----------------
// C[z] (MxN) = Ahat[z] (MxK) * B[z] (KxN), with Ahat supplied TRANSPOSED:
// AT is [K][M] row-major (weights pre-rounded to tf32).
// CONV: B is im2col(y[z]) with k = c*9 + r.  CVTB: round B frags at use.
template <int CONV, int CVTB>
__global__ __launch_bounds__(256)
void tgemm(const float* __restrict__ AT, long lA,
           const float* __restrict__ B, long lB,
           float* __restrict__ C, long lC, int ldC,
           int M, int N, int K, int roundC)
{
    extern __shared__ float sm[];
    AT += (long)blockIdx.z * lA;
    B  += (long)blockIdx.z * lB;
    C  += (long)blockIdx.z * lC;
    const int bm = blockIdx.y * 128;
    const int bn = blockIdx.x * 128;

    const int tid  = threadIdx.x;
    const int lane = tid & 31, warp = tid >> 5;
    const int wm = (warp >> 2) * 64, wn = (warp & 3) * 32;
    const int g = lane >> 2, t = lane & 3;

    float* As = sm;
    float* Bs = sm + STAGES * ASTG;
    const uint32_t aBase = (uint32_t)__cvta_generic_to_shared(As);
    const uint32_t bBase = (uint32_t)__cvta_generic_to_shared(Bs);

    // A / dense-B load coords
    const int lrow = tid >> 5;          // 0..7 (+8 for second)
    const int lcol = (tid & 31) * 4;

    // conv loader state
    int cIc = 0, cR = 0, cKrow = 0, cJ0 = 0, cH = 0, cW0 = 0;
    if (CONV) {
        cKrow = tid >> 4;               // 0..15
        cJ0   = (tid & 15) * 8;
        const int n0 = bn + cJ0;
        cH  = n0 >> 6;
        cW0 = n0 & 63;
        cIc = cKrow >= 9 ? 1 : 0;
        cR  = cKrow - 9 * cIc;
    }

    float acc[4][4][4];
#pragma unroll
    for (int i = 0; i < 4; i++)
#pragma unroll
        for (int j = 0; j < 4; j++)
#pragma unroll
            for (int r = 0; r < 4; r++) acc[i][j][r] = 0.f;

    const int T = K >> 4;

    auto load_stage = [&](int s, int k0) {
        // A tile: AT rows k0..k0+15, cols bm..bm+127
        const uint32_t aDst = aBase + (uint32_t)(s * ASTG + lrow * SSTR + lcol) * 4u;
        const float* aSrc = AT + (long)(k0 + lrow) * M + bm + lcol;
        cpa16(aDst, aSrc);
        cpa16(aDst + 8u * SSTR * 4u, aSrc + 8L * M);
        if (!CONV) {
            const uint32_t bDst = bBase + (uint32_t)(s * ASTG + lrow * SSTR + lcol) * 4u;
            const float* bSrc = B + (long)(k0 + lrow) * N + bn + lcol;
            cpa16(bDst, bSrc);
            cpa16(bDst + 8u * SSTR * 4u, bSrc + 8L * N);
        } else {
            const int dyr = (cR * 11) >> 5;       // cR/3
            const int dy = dyr - 1;
            const int dx = cR - 3 * dyr - 1;
            const int hh = cH + dy;
            const bool hok = (unsigned)hh < 64u;
            const float* rowp = B + ((long)cIc * 64 + hh) * 64;
            uint32_t dst = bBase + (uint32_t)(s * ASTG + cKrow * SSTR + cJ0) * 4u;
#pragma unroll
            for (int u = 0; u < 8; u++) {
                const int ww = cW0 + dx + u;
                const bool ok = hok && ((unsigned)ww < 64u);
                cpa4z(dst + 4u * u, ok ? (rowp + ww) : B, ok ? 4 : 0);
            }
            // advance (ic, r) by k += 16
            cR += 7; cIc += 1;
            if (cR >= 9) { cR -= 9; cIc += 1; }
        }
    };

    // prologue: stages 0,1
    load_stage(0, 0);  CP_COMMIT();
    load_stage(1, 16); CP_COMMIT();

    for (int tt = 0; tt < T; tt++) {
        CP_WAIT1();
        __syncthreads();
        if (tt + 2 < T) load_stage((tt + 2) % STAGES, (tt + 2) * TILEK);
        CP_COMMIT();

        const float* As_ = As + (tt % STAGES) * ASTG;
        const float* Bs_ = Bs + (tt % STAGES) * ASTG;
#pragma unroll
        for (int k8 = 0; k8 < 2; k8++) {
            const float* a0 = As_ + (k8 * 8 + t) * SSTR;
            const float* a1 = a0 + 4 * SSTR;
            const float* b0 = Bs_ + (k8 * 8 + t) * SSTR;
            const float* b1 = b0 + 4 * SSTR;
            uint32_t af[4][4], bf[4][2];
#pragma unroll
            for (int mi = 0; mi < 4; mi++) {
                const int m0 = wm + mi * 16 + g;
                af[mi][0] = __float_as_uint(a0[m0]);
                af[mi][1] = __float_as_uint(a0[m0 + 8]);
                af[mi][2] = __float_as_uint(a1[m0]);
                af[mi][3] = __float_as_uint(a1[m0 + 8]);
            }
#pragma unroll
            for (int ni = 0; ni < 4; ni++) {
                const int n0 = wn + ni * 8 + g;
                const float x0 = b0[n0], x1 = b1[n0];
                bf[ni][0] = CVTB ? f2tf32(x0) : __float_as_uint(x0);
                bf[ni][1] = CVTB ? f2tf32(x1) : __float_as_uint(x1);
            }
#pragma unroll
            for (int mi = 0; mi < 4; mi++)
#pragma unroll
                for (int ni = 0; ni < 4; ni++)
                    mma8(acc[mi][ni][0], acc[mi][ni][1], acc[mi][ni][2], acc[mi][ni][3],
                         af[mi][0], af[mi][1], af[mi][2], af[mi][3],
                         bf[ni][0], bf[ni][1]);
        }
    }

    const bool rnd = (roundC == 1) || (roundC == 2 && bm >= 512);
#pragma unroll
    for (int mi = 0; mi < 4; mi++) {
        const int row0 = bm + wm + mi * 16 + g;
#pragma unroll
        for (int ni = 0; ni < 4; ni++) {
            const int col = bn + wn + ni * 8 + 2 * t;
            float v0 = acc[mi][ni][0], v1 = acc[mi][ni][1];
            float v2 = acc[mi][ni][2], v3 = acc[mi][ni][3];
            if (rnd) { v0 = rndf(v0); v1 = rndf(v1); v2 = rndf(v2); v3 = rndf(v3); }
            *(float2*)(C + (long)row0 * ldC + col)       = make_float2(v0, v1);
            *(float2*)(C + (long)(row0 + 8) * ldC + col) = make_float2(v2, v3);
        }
    }
}

// ---------------- prep kernels (weights -> rounded / transposed) ----------
__global__ void prep_wq(const float* __restrict__ wq, float* __restrict__ wqR) {
    const int i = blockIdx.x * blockDim.x + threadIdx.x;
    if (i < DIM * DIM) wqR[i] = rndf(wq[i]);
}
__global__ void prep_wkvT(const float* __restrict__ wkv, float* __restrict__ wkvT) {
    __shared__ float tile[32][33];
    const int o0 = blockIdx.x * 32, c0 = blockIdx.y * 32;
    const int tx = threadIdx.x & 31, ty = threadIdx.x >> 5;
#pragma unroll
    for (int k = 0; k < 32; k += 8)
        tile[ty + k][tx] = wkv[(long)(o0 + ty + k) * DIM + c0 + tx];
    __syncthreads();
#pragma unroll
    for (int k = 0; k < 32; k += 8)
        wkvT[(long)(c0 + ty + k) * (2 * DIM) + o0 + tx] = rndf(tile[tx][ty + k]);
}
__global__ void prep_wdw(const float* __restrict__ wdw, float* __restrict__ wdwTr) {
    __shared__ float s[32][288];
    const int o20 = blockIdx.x * 32, o0 = blockIdx.y * 32;
    for (int idx = threadIdx.x; idx < 32 * 288; idx += 256) {
        const int seg = idx / 288, off = idx - seg * 288;
        s[seg][off] = wdw[((long)(o20 + seg) * DIM + o0) * 9 + off];
    }
    __syncthreads();
    for (int idx = threadIdx.x; idx < 9 * 32 * 32; idx += 256) {
        const int r = idx >> 10, ol = (idx >> 5) & 31, o2l = idx & 31;
        wdwTr[(long)r * (DIM * DIM) + (long)(o0 + ol) * DIM + o20 + o2l] =
            rndf(s[o2l][ol * 9 + r]);
    }
}

// ---------------- attention logits (m split 8 ways) + fused sumsq ---------
__global__ __launch_bounds__(256)
void attn_partial_kernel(const float* __restrict__ Q,
                         const float* __restrict__ KV,
                         float* __restrict__ part,
                         float* __restrict__ nsq)
{
    const int mc = blockIdx.x;
    const int h  = blockIdx.y;
    const int b  = blockIdx.z;
    const float* Qp = Q  + ((long)(b * DIM + h * HD)) * MLEN + mc * 512;
    const float* Kp = KV + ((long)(b * 2 * DIM + h * HD)) * MLEN + mc * 512;

    __shared__ float sq[32][64];
    __shared__ float sk[32][64];

    const int tid = threadIdx.x;
    const int row = tid >> 2;
    const int mg  = (tid & 3) * 8;
    const int tx  = tid & 15;
    const int ty  = tid >> 4;

    float acc[4][4];
#pragma unroll
    for (int i = 0; i < 4; i++)
#pragma unroll
        for (int j = 0; j < 4; j++) acc[i][j] = 0.f;

    float ssq = 0.f, ssk = 0.f;

    for (int mt = 0; mt < 512; mt += 32) {
        float4 a0 = *(const float4*)(Qp + (long)row * MLEN + mt + mg);
        float4 a1 = *(const float4*)(Qp + (long)row * MLEN + mt + mg + 4);
        sq[mg + 0][row] = a0.x; sq[mg + 1][row] = a0.y;
        sq[mg + 2][row] = a0.z; sq[mg + 3][row] = a0.w;
        sq[mg + 4][row] = a1.x; sq[mg + 5][row] = a1.y;
        sq[mg + 6][row] = a1.z; sq[mg + 7][row] = a1.w;
        ssq += a0.x*a0.x + a0.y*a0.y + a0.z*a0.z + a0.w*a0.w
             + a1.x*a1.x + a1.y*a1.y + a1.z*a1.z + a1.w*a1.w;
        float4 b0 = *(const float4*)(Kp + (long)row * MLEN + mt + mg);
        float4 b1 = *(const float4*)(Kp + (long)row * MLEN + mt + mg + 4);
        sk[mg + 0][row] = b0.x; sk[mg + 1][row] = b0.y;
        sk[mg + 2][row] = b0.z; sk[mg + 3][row] = b0.w;
        sk[mg + 4][row] = b1.x; sk[mg + 5][row] = b1.y;
        sk[mg + 6][row] = b1.z; sk[mg + 7][row] = b1.w;
        ssk += b0.x*b0.x + b0.y*b0.y + b0.z*b0.z + b0.w*b0.w
             + b1.x*b1.x + b1.y*b1.y + b1.z*b1.z + b1.w*b1.w;
        __syncthreads();
#pragma unroll
        for (int mm = 0; mm < 32; mm++) {
            float ra[4], rb[4];
#pragma unroll
            for (int i = 0; i < 4; i++) ra[i] = sq[mm][ty * 4 + i];
#pragma unroll
            for (int j = 0; j < 4; j++) rb[j] = sk[mm][tx * 4 + j];
#pragma unroll
            for (int i = 0; i < 4; i++)
#pragma unroll
                for (int j = 0; j < 4; j++) acc[i][j] += ra[i] * rb[j];
        }
        __syncthreads();
    }
    // reduce sumsq across the 4 loader threads of each row (lane bits 0,1)
    ssq += __shfl_xor_sync(~0u, ssq, 1); ssq += __shfl_xor_sync(~0u, ssq, 2);
    ssk += __shfl_xor_sync(~0u, ssk, 1); ssk += __shfl_xor_sync(~0u, ssk, 2);
    if ((tid & 3) == 0) {
        const long nb = (((long)(b * HEADS + h)) * 8 + mc) * 2 * HD;
        nsq[nb + row]      = ssq;
        nsq[nb + HD + row] = ssk;
    }
    float* pp = part + ((((long)(b * HEADS + h)) * 8 + mc) * HD + ty * 4) * HD + tx * 4;
#pragma unroll
    for (int i = 0; i < 4; i++)
#pragma unroll
        for (int j = 0; j < 4; j++) pp[i * HD + j] = acc[i][j];
}

// ---------------- reduce partials + norms + temperature + softmax ---------
__global__ void softmax_kernel(const float* __restrict__ part,
                               const float* __restrict__ nsq,
                               const float* __restrict__ temp,
                               float* __restrict__ attn)
{
    const int row = blockIdx.x;          // 0..2047
    const int b = row >> 9;
    const int h = (row >> 6) & 7;
    const int c = row & 63;
    const int lane = threadIdx.x;        // 32

    const long nb = ((long)(b * HEADS + h)) * 8 * 2 * HD;
    float sqs = 0.f, sk0 = 0.f, sk1 = 0.f;
#pragma unroll
    for (int mc = 0; mc < 8; mc++) {
        sqs += nsq[nb + mc * 2 * HD + c];
        sk0 += nsq[nb + mc * 2 * HD + HD + lane];
        sk1 += nsq[nb + mc * 2 * HD + HD + lane + 32];
    }
    const float rq  = 1.f / fmaxf(sqrtf(sqs), 1e-12f);
    const float rk0 = 1.f / fmaxf(sqrtf(sk0), 1e-12f);
    const float rk1 = 1.f / fmaxf(sqrtf(sk1), 1e-12f);
    const float tq = rq * temp[h];

    float v[2];
    {
        const long base = (((long)(b * HEADS + h)) * 8) * (HD * HD) + c * HD;
        float s0 = 0.f, s1 = 0.f;
#pragma unroll
        for (int mc = 0; mc < 8; mc++) {
            s0 += part[base + (long)mc * (HD * HD) + lane];
            s1 += part[base + (long)mc * (HD * HD) + lane + 32];
        }
        v[0] = s0 * tq * rk0;
        v[1] = s1 * tq * rk1;
    }
    float mx = fmaxf(v[0], v[1]);
#pragma unroll
    for (int o = 16; o; o >>= 1) mx = fmaxf(mx, __shfl_xor_sync(~0u, mx, o));
    const float e0 = expf(v[0] - mx);
    const float e1 = expf(v[1] - mx);
    float s = e0 + e1;
#pragma unroll
    for (int o = 16; o; o >>= 1) s += __shfl_xor_sync(~0u, s, o);
    const float inv = 1.f / s;
    float* ap = attn + (((long)(b * HEADS + h)) * HD + c) * HD;
    ap[lane]      = e0 * inv;
    ap[lane + 32] = e1 * inv;
}

// ---------------- W2T[k][o] = (w_out @ blockdiag(attn))^T, tf32-rounded ----
__global__ void w2_kernel(const float* __restrict__ w_out,
                          const float* __restrict__ attn,
                          float* __restrict__ W2T)
{
    const int b = blockIdx.z;
    const int h = blockIdx.y;
    const int tid = threadIdx.x;
    __shared__ float sa[HD * HD];
    __shared__ float sa2[4][HD];
    const float* ap = attn + ((long)(b * HEADS + h)) * HD * HD;
    for (int i = tid; i < HD * HD; i += 256) sa[i] = ap[i];
    __syncthreads();
    const int o = blockIdx.x * 4 + (tid >> 6);
    const int d = tid & 63;
    const float* wrow = w_out + (long)o * DIM + h * HD;
    float acc = 0.f;
#pragma unroll
    for (int c = 0; c < HD; c++) acc += wrow[c] * sa[c * HD + d];
    sa2[tid >> 6][d] = acc;
    __syncthreads();
    if (tid < 64) {
        float4 vv = make_float4(rndf(sa2[0][tid]), rndf(sa2[1][tid]),
                                rndf(sa2[2][tid]), rndf(sa2[3][tid]));
        *(float4*)&W2T[((long)b * DIM + h * HD + tid) * DIM + blockIdx.x * 4] = vv;
    }
}

// ---------------- launcher ----------------
extern "C" void kernel_launch(void* const* d_in, const int* in_sizes, int n_in,
                              void* d_out, int out_size)
{
    const float* x    = (const float*)d_in[0];
    const float* y    = (const float*)d_in[1];
    const float* temp = (const float*)d_in[2];
    const float* wkv  = (const float*)d_in[3];
    const float* wq   = (const float*)d_in[4];
    const float* wdw  = (const float*)d_in[5];
    const float* wout = (const float*)d_in[6];
    float* out = (float*)d_out;

    float *kv, *q, *part, *nsq, *attn, *w2T, *wkvT, *wqR, *wdwTr, *wc;
    cudaGetSymbolAddress((void**)&kv,    g_kv);
    cudaGetSymbolAddress((void**)&q,     g_q);
    cudaGetSymbolAddress((void**)&part,  g_part);
    cudaGetSymbolAddress((void**)&nsq,   g_nsq);
    cudaGetSymbolAddress((void**)&attn,  g_attn);
    cudaGetSymbolAddress((void**)&w2T,   g_w2T);
    cudaGetSymbolAddress((void**)&wkvT,  g_wkvT);
    cudaGetSymbolAddress((void**)&wqR,   g_wqR);
    cudaGetSymbolAddress((void**)&wdwTr, g_wdwTr);
    cudaGetSymbolAddress((void**)&wc,    g_wc);

    cudaFuncSetAttribute(tgemm<0,0>, cudaFuncAttributeMaxDynamicSharedMemorySize, SMEMB);
    cudaFuncSetAttribute(tgemm<0,1>, cudaFuncAttributeMaxDynamicSharedMemorySize, SMEMB);
    cudaFuncSetAttribute(tgemm<1,1>, cudaFuncAttributeMaxDynamicSharedMemorySize, SMEMB);

    // 0) weight prep (round to tf32, transpose)
    prep_wq  <<<512, 512>>>(wq, wqR);
    prep_wkvT<<<dim3(32, 16), 256>>>(wkv, wkvT);
    prep_wdw <<<dim3(16, 16), 256>>>(wdw, wdwTr);

    // 1) WcT[c*9+r][o2] = sum_o wq[o][c] * wdw[o2][o][r]   (9 GEMMs 512^3)
    tgemm<0,0><<<dim3(4, 4, 9), 256, SMEMB>>>(
        wqR, 0L, wdwTr, (long)DIM * DIM, wc, 512L, KCONV,
        DIM, DIM, DIM, 1);

    // 2) kv = w_kv @ x   (1024 x 4096, K=512); round v half
    tgemm<0,1><<<dim3(32, 8, BATCH), 256, SMEMB>>>(
        wkvT, 0L, x, (long)DIM * MLEN, kv, (long)2 * DIM * MLEN, MLEN,
        2 * DIM, MLEN, DIM, 2);

    // 3) q = Wc (*) im2col(y)   (512 x 4096, K=4608) — q1 GEMM fused away
    tgemm<1,1><<<dim3(32, 4, BATCH), 256, SMEMB>>>(
        wc, 0L, y, (long)DIM * MLEN, q, (long)DIM * MLEN, MLEN,
        DIM, MLEN, KCONV, 0);

    // 4) attention logits + fused row sumsq
    attn_partial_kernel<<<dim3(8, HEADS, BATCH), 256>>>(q, kv, part, nsq);

    // 5) reduce + norms + temperature + softmax
    softmax_kernel<<<BATCH * HEADS * HD, 32>>>(part, nsq, temp, attn);

    // 6) W2T = (w_out @ blockdiag(attn))^T, rounded
    w2_kernel<<<dim3(128, HEADS, BATCH), 256>>>(wout, attn, w2T);

    // 7) out = W2 @ v
    tgemm<0,0><<<dim3(32, 4, BATCH), 256, SMEMB>>>(
        w2T, (long)DIM * DIM, kv + (long)DIM * MLEN, (long)2 * DIM * MLEN,
        out, (long)DIM * MLEN, MLEN,
        DIM, MLEN, DIM, 0);
}

// round 6
// speedup vs baseline: 5.4427x; 1.8414x over previous
#include <cuda_runtime.h>
#include <cuda_fp16.h>
#include <math.h>
#include <stdint.h>

#define BATCH 4
#define DIM   512
#define MLEN  4096
#define HEADS 8
#define HD    64
#define KCONV 4608
#define YROWS 4356
#define SMEMB 61440   // 3 stages * (A 10240 + B 10240)

// ---------------- static scratch ----------------
__device__ float  g_kv  [BATCH*2*DIM*MLEN];
__device__ float  g_q   [BATCH*DIM*MLEN];
__device__ float  g_part[BATCH*HEADS*8*HD*HD];
__device__ float  g_nsq [BATCH*HEADS*8*2*HD];
__device__ float  g_attn[BATCH*HEADS*HD*HD];
__device__ __half g_xTh [BATCH*MLEN*DIM];
__device__ __half g_yTh [BATCH*YROWS*DIM];
__device__ __half g_vTh [BATCH*MLEN*DIM];
__device__ __half g_wkvh[2*DIM*DIM];
__device__ __half g_wqTh[DIM*DIM];
__device__ __half g_wdwh[9*DIM*DIM];
__device__ __half g_wc2h[DIM*KCONV];
__device__ __half g_w2h [BATCH*DIM*DIM];

// ---------------- helpers ----------------
__device__ __forceinline__ void cpa16(uint32_t d, const void* s){
    asm volatile("cp.async.cg.shared.global [%0], [%1], 16;" :: "r"(d), "l"(s));
}
#define CP_COMMIT() asm volatile("cp.async.commit_group;")
#define CP_WAIT1()  asm volatile("cp.async.wait_group 1;")

__device__ __forceinline__ void mma16(float& c0, float& c1, float& c2, float& c3,
                                      uint32_t a0, uint32_t a1, uint32_t a2, uint32_t a3,
                                      uint32_t b0, uint32_t b1){
    asm volatile(
        "mma.sync.aligned.m16n8k16.row.col.f32.f16.f16.f32 "
        "{%0,%1,%2,%3}, {%4,%5,%6,%7}, {%8,%9}, {%0,%1,%2,%3};"
        : "+f"(c0), "+f"(c1), "+f"(c2), "+f"(c3)
        : "r"(a0), "r"(a1), "r"(a2), "r"(a3), "r"(b0), "r"(b1));
}

// ---------------- fp16 tensor GEMM, cp.async 3-stage ----------------
// C[z](MxN) = A[z](MxK fp16 row-major) * B[z]^T, B n-major [n][K] fp16
// (or conv: B = padded transposed image yT, k = r*512 + c).
// Block 128x128, BK=32, 8 warps, warp tile 64x32.
// smem per stage: A 128 rows x 40 halves (80B, 64B data+16B pad), B same.
template<int CONV, int OUTH>
__global__ __launch_bounds__(256, 2)
void hgemm(const __half* __restrict__ A, long lA,
           const __half* __restrict__ B, long lB,
           void* __restrict__ Cv, long lC, int ldC,
           int M, int K)
{
    extern __shared__ __half sh[];
    const uint32_t smb = (uint32_t)__cvta_generic_to_shared(sh);
    A += (long)blockIdx.z * lA;
    B += (long)blockIdx.z * lB;
    const int bm = blockIdx.y * 128, bn = blockIdx.x * 128;
    const int tid = threadIdx.x, lane = tid & 31, warp = tid >> 5;
    const int wm = (warp >> 2) * 64, wn = (warp & 3) * 32;
    const int g = lane >> 2, t = lane & 3;

    const int lrow = tid >> 1;          // 0..127
    const int lco  = (tid & 1) * 16;    // halves 0 / 16

    int ph = 0, pw = 0;
    if (CONV) { const int n = bn + lrow; ph = n >> 6; pw = n & 63; }

    float acc[4][4][4];
#pragma unroll
    for (int i = 0; i < 4; i++)
#pragma unroll
        for (int j = 0; j < 4; j++)
#pragma unroll
            for (int r = 0; r < 4; r++) acc[i][j][r] = 0.f;

    const int T = K >> 5;

    auto load = [&](int s, int tt){
        const int k0 = tt << 5;
        const uint32_t sb = smb + (uint32_t)s * 20480u;
        const __half* asrc = A + (long)(bm + lrow) * K + k0 + lco;
        const uint32_t adst = sb + (uint32_t)lrow * 80u + (uint32_t)lco * 2u;
        cpa16(adst,       asrc);
        cpa16(adst + 16u, asrc + 8);
        const __half* bsrc;
        if (CONV) {
            const int r = k0 >> 9;
            const int dyr = r / 3, dxr = r - 3 * dyr;
            bsrc = B + ((long)((ph + dyr) * 66 + pw + dxr)) * DIM + (k0 & 511) + lco;
        } else {
            bsrc = B + (long)(bn + lrow) * K + k0 + lco;
        }
        const uint32_t bdst = sb + 10240u + (uint32_t)lrow * 80u + (uint32_t)lco * 2u;
        cpa16(bdst,       bsrc);
        cpa16(bdst + 16u, bsrc + 8);
    };

    load(0, 0); CP_COMMIT();
    load(1, 1); CP_COMMIT();

    const uint32_t* sw = (const uint32_t*)sh;

    for (int tt = 0; tt < T; tt++) {
        const int s = tt % 3;
        CP_WAIT1();
        __syncthreads();
        if (tt + 2 < T) load((tt + 2) % 3, tt + 2);
        CP_COMMIT();

        const int stW = s * 5120;       // words per stage
#pragma unroll
        for (int ks = 0; ks < 2; ks++) {
            const int kq = ks * 8;
            const uint32_t* ap = sw + stW + kq + t;
            const uint32_t* bp = sw + stW + 2560 + kq + t;
            uint32_t af[4][4], bf[4][2];
#pragma unroll
            for (int mi = 0; mi < 4; mi++) {
                const int m0 = (wm + mi * 16 + g) * 20;
                af[mi][0] = ap[m0];
                af[mi][1] = ap[m0 + 160];   // +8 rows
                af[mi][2] = ap[m0 + 4];
                af[mi][3] = ap[m0 + 164];
            }
#pragma unroll
            for (int ni = 0; ni < 4; ni++) {
                const int n0 = (wn + ni * 8 + g) * 20;
                bf[ni][0] = bp[n0];
                bf[ni][1] = bp[n0 + 4];
            }
#pragma unroll
            for (int mi = 0; mi < 4; mi++)
#pragma unroll
                for (int ni = 0; ni < 4; ni++)
                    mma16(acc[mi][ni][0], acc[mi][ni][1], acc[mi][ni][2], acc[mi][ni][3],
                          af[mi][0], af[mi][1], af[mi][2], af[mi][3],
                          bf[ni][0], bf[ni][1]);
        }
    }

    if (OUTH) {
        __half* C = (__half*)Cv + (long)blockIdx.z * lC;
#pragma unroll
        for (int mi = 0; mi < 4; mi++) {
            const int row0 = bm + wm + mi * 16 + g;
#pragma unroll
            for (int ni = 0; ni < 4; ni++) {
                const int col = bn + wn + ni * 8 + 2 * t;
                *(__half2*)(C + (long)row0 * ldC + col) =
                    __floats2half2_rn(acc[mi][ni][0], acc[mi][ni][1]);
                *(__half2*)(C + (long)(row0 + 8) * ldC + col) =
                    __floats2half2_rn(acc[mi][ni][2], acc[mi][ni][3]);
            }
        }
    } else {
        float* C = (float*)Cv + (long)blockIdx.z * lC;
#pragma unroll
        for (int mi = 0; mi < 4; mi++) {
            const int row0 = bm + wm + mi * 16 + g;
#pragma unroll
            for (int ni = 0; ni < 4; ni++) {
                const int col = bn + wn + ni * 8 + 2 * t;
                *(float2*)(C + (long)row0 * ldC + col) =
                    make_float2(acc[mi][ni][0], acc[mi][ni][1]);
                *(float2*)(C + (long)(row0 + 8) * ldC + col) =
                    make_float2(acc[mi][ni][2], acc[mi][ni][3]);
            }
        }
    }
}

// ---------------- prep / transpose kernels ----------------
__global__ void conv_h(const float* __restrict__ s, __half* __restrict__ d, int n){
    const int i = blockIdx.x * 256 + threadIdx.x;
    if (i < n) d[i] = __float2half_rn(s[i]);
}

// S [c][m] fp32 -> D [m][c] fp16 (PADY: into padded 66x66 image rows)
template<int PADY>
__global__ void transpose_h(const float* __restrict__ S, long lS,
                            __half* __restrict__ D, long lD, int R, int C)
{
    __shared__ float tle[32][33];
    S += (long)blockIdx.z * lS;
    D += (long)blockIdx.z * lD;
    const int m0 = blockIdx.x * 32, c0 = blockIdx.y * 32;
    const int tx = threadIdx.x & 31, ty = threadIdx.x >> 5;
#pragma unroll
    for (int i = ty; i < 32; i += 8)
        tle[i][tx] = S[(long)(c0 + i) * C + m0 + tx];
    __syncthreads();
    const long prow = PADY ? (long)(m0 + 2 * (m0 >> 6) + 67) : (long)m0;
#pragma unroll
    for (int i = ty; i < 32; i += 8)
        D[(prow + i) * R + c0 + tx] = __float2half_rn(tle[tx][i]);
}

__global__ void ypad_zero_h(__half* __restrict__ yT)
{
    const int idx = blockIdx.x;
    int row;
    if (idx < 66) row = idx;
    else if (idx < 132) row = 65 * 66 + (idx - 66);
    else { const int i = idx - 132; row = (1 + (i >> 1)) * 66 + (i & 1) * 65; }
    uint32_t* p = (uint32_t*)(yT + ((long)blockIdx.y * YROWS + row) * DIM);
    p[threadIdx.x] = 0u;
}

// wdwh[r][o2][o] = wdw[o2][o][r]  (fp16)
__global__ void prep_wdw_h(const float* __restrict__ wdw, __half* __restrict__ wdwh)
{
    __shared__ float s[KCONV];
    const int o2 = blockIdx.x;
    const float* src = wdw + (long)o2 * KCONV;
    for (int i = threadIdx.x; i < KCONV; i += 256) s[i] = src[i];
    __syncthreads();
    for (int i = threadIdx.x; i < KCONV; i += 256) {
        const int r = i >> 9, o = i & 511;
        wdwh[((long)r * DIM + o2) * DIM + o] = __float2half_rn(s[o * 9 + r]);
    }
}

// ---------------- attention logits + fused sumsq ----------------
__global__ __launch_bounds__(256)
void attn_partial_kernel(const float* __restrict__ Q, const float* __restrict__ KV,
                         float* __restrict__ part, float* __restrict__ nsq)
{
    const int mc = blockIdx.x, h = blockIdx.y, b = blockIdx.z;
    const float* Qp = Q  + ((long)(b * DIM + h * HD)) * MLEN + mc * 512;
    const float* Kp = KV + ((long)(b * 2 * DIM + h * HD)) * MLEN + mc * 512;
    __shared__ float sq[32][64];
    __shared__ float sk[32][64];
    const int tid = threadIdx.x, row = tid >> 2, mg = (tid & 3) * 8;
    const int tx = tid & 15, ty = tid >> 4;
    float acc[4][4];
#pragma unroll
    for (int i = 0; i < 4; i++)
#pragma unroll
        for (int j = 0; j < 4; j++) acc[i][j] = 0.f;
    float ssq = 0.f, ssk = 0.f;
    for (int mt = 0; mt < 512; mt += 32) {
        float4 a0 = *(const float4*)(Qp + (long)row * MLEN + mt + mg);
        float4 a1 = *(const float4*)(Qp + (long)row * MLEN + mt + mg + 4);
        sq[mg+0][row]=a0.x; sq[mg+1][row]=a0.y; sq[mg+2][row]=a0.z; sq[mg+3][row]=a0.w;
        sq[mg+4][row]=a1.x; sq[mg+5][row]=a1.y; sq[mg+6][row]=a1.z; sq[mg+7][row]=a1.w;
        ssq += a0.x*a0.x+a0.y*a0.y+a0.z*a0.z+a0.w*a0.w + a1.x*a1.x+a1.y*a1.y+a1.z*a1.z+a1.w*a1.w;
        float4 b0 = *(const float4*)(Kp + (long)row * MLEN + mt + mg);
        float4 b1 = *(const float4*)(Kp + (long)row * MLEN + mt + mg + 4);
        sk[mg+0][row]=b0.x; sk[mg+1][row]=b0.y; sk[mg+2][row]=b0.z; sk[mg+3][row]=b0.w;
        sk[mg+4][row]=b1.x; sk[mg+5][row]=b1.y; sk[mg+6][row]=b1.z; sk[mg+7][row]=b1.w;
        ssk += b0.x*b0.x+b0.y*b0.y+b0.z*b0.z+b0.w*b0.w + b1.x*b1.x+b1.y*b1.y+b1.z*b1.z+b1.w*b1.w;
        __syncthreads();
#pragma unroll
        for (int mm = 0; mm < 32; mm++) {
            float ra[4], rb[4];
#pragma unroll
            for (int i = 0; i < 4; i++) ra[i] = sq[mm][ty*4+i];
#pragma unroll
            for (int j = 0; j < 4; j++) rb[j] = sk[mm][tx*4+j];
#pragma unroll
            for (int i = 0; i < 4; i++)
#pragma unroll
                for (int j = 0; j < 4; j++) acc[i][j] += ra[i]*rb[j];
        }
        __syncthreads();
    }
    ssq += __shfl_xor_sync(~0u, ssq, 1); ssq += __shfl_xor_sync(~0u, ssq, 2);
    ssk += __shfl_xor_sync(~0u, ssk, 1); ssk += __shfl_xor_sync(~0u, ssk, 2);
    if ((tid & 3) == 0) {
        const long nb = (((long)(b*HEADS + h))*8 + mc) * 2 * HD;
        nsq[nb + row] = ssq;
        nsq[nb + HD + row] = ssk;
    }
    float* pp = part + ((((long)(b*HEADS + h))*8 + mc)*HD + ty*4)*HD + tx*4;
#pragma unroll
    for (int i = 0; i < 4; i++)
#pragma unroll
        for (int j = 0; j < 4; j++) pp[i*HD + j] = acc[i][j];
}

__global__ void softmax_kernel(const float* __restrict__ part, const float* __restrict__ nsq,
                               const float* __restrict__ temp, float* __restrict__ attn)
{
    const int row = blockIdx.x;
    const int b = row >> 9, h = (row >> 6) & 7, c = row & 63;
    const int lane = threadIdx.x;
    const long nb = ((long)(b*HEADS + h)) * 8 * 2 * HD;
    float sqs = 0.f, sk0 = 0.f, sk1 = 0.f;
#pragma unroll
    for (int mc = 0; mc < 8; mc++) {
        sqs += nsq[nb + mc*2*HD + c];
        sk0 += nsq[nb + mc*2*HD + HD + lane];
        sk1 += nsq[nb + mc*2*HD + HD + lane + 32];
    }
    const float rq  = 1.f / fmaxf(sqrtf(sqs), 1e-12f);
    const float rk0 = 1.f / fmaxf(sqrtf(sk0), 1e-12f);
    const float rk1 = 1.f / fmaxf(sqrtf(sk1), 1e-12f);
    const float tq = rq * temp[h];
    const long base = (((long)(b*HEADS + h)) * 8) * (HD*HD) + c*HD;
    float s0 = 0.f, s1 = 0.f;
#pragma unroll
    for (int mc = 0; mc < 8; mc++) {
        s0 += part[base + (long)mc*(HD*HD) + lane];
        s1 += part[base + (long)mc*(HD*HD) + lane + 32];
    }
    float v0 = s0 * tq * rk0, v1 = s1 * tq * rk1;
    float mx = fmaxf(v0, v1);
#pragma unroll
    for (int o = 16; o; o >>= 1) mx = fmaxf(mx, __shfl_xor_sync(~0u, mx, o));
    const float e0 = expf(v0 - mx), e1 = expf(v1 - mx);
    float s = e0 + e1;
#pragma unroll
    for (int o = 16; o; o >>= 1) s += __shfl_xor_sync(~0u, s, o);
    const float inv = 1.f / s;
    float* ap = attn + (((long)(b*HEADS + h))*HD + c)*HD;
    ap[lane] = e0 * inv;
    ap[lane + 32] = e1 * inv;
}

// ---------------- W2h = half(w_out @ blockdiag(attn)) ----------------
__global__ void w2_kernel_h(const float* __restrict__ w_out, const float* __restrict__ attn,
                            __half* __restrict__ W2h)
{
    const int b = blockIdx.z, h = blockIdx.y;
    const int tid = threadIdx.x;
    __shared__ float sa[HD*HD];
    const float* ap = attn + ((long)(b*HEADS + h)) * HD * HD;
    for (int i = tid; i < HD*HD; i += 256) sa[i] = ap[i];
    __syncthreads();
    const int o = blockIdx.x * 4 + (tid >> 6);
    const int d = tid & 63;
    const float* wrow = w_out + (long)o * DIM + h * HD;
    float acc = 0.f;
#pragma unroll
    for (int c = 0; c < HD; c++) acc += wrow[c] * sa[c*HD + d];
    W2h[((long)b*DIM + o) * DIM + h*HD + d] = __float2half_rn(acc);
}

// ---------------- launcher ----------------
extern "C" void kernel_launch(void* const* d_in, const int* in_sizes, int n_in,
                              void* d_out, int out_size)
{
    const float* x    = (const float*)d_in[0];
    const float* y    = (const float*)d_in[1];
    const float* temp = (const float*)d_in[2];
    const float* wkv  = (const float*)d_in[3];
    const float* wq   = (const float*)d_in[4];
    const float* wdw  = (const float*)d_in[5];
    const float* wout = (const float*)d_in[6];
    float* out = (float*)d_out;

    float *kv, *q, *part, *nsq, *attn;
    __half *xTh, *yTh, *vTh, *wkvh, *wqTh, *wdwh, *wc2h, *w2h;
    cudaGetSymbolAddress((void**)&kv,   g_kv);
    cudaGetSymbolAddress((void**)&q,    g_q);
    cudaGetSymbolAddress((void**)&part, g_part);
    cudaGetSymbolAddress((void**)&nsq,  g_nsq);
    cudaGetSymbolAddress((void**)&attn, g_attn);
    cudaGetSymbolAddress((void**)&xTh,  g_xTh);
    cudaGetSymbolAddress((void**)&yTh,  g_yTh);
    cudaGetSymbolAddress((void**)&vTh,  g_vTh);
    cudaGetSymbolAddress((void**)&wkvh, g_wkvh);
    cudaGetSymbolAddress((void**)&wqTh, g_wqTh);
    cudaGetSymbolAddress((void**)&wdwh, g_wdwh);
    cudaGetSymbolAddress((void**)&wc2h, g_wc2h);
    cudaGetSymbolAddress((void**)&w2h,  g_w2h);

    cudaFuncSetAttribute(hgemm<0,0>, cudaFuncAttributeMaxDynamicSharedMemorySize, SMEMB);
    cudaFuncSetAttribute(hgemm<0,1>, cudaFuncAttributeMaxDynamicSharedMemorySize, SMEMB);
    cudaFuncSetAttribute(hgemm<1,0>, cudaFuncAttributeMaxDynamicSharedMemorySize, SMEMB);

    // weight prep (fp16)
    conv_h<<<2048, 256>>>(wkv, wkvh, 2*DIM*DIM);
    prep_wdw_h<<<512, 256>>>(wdw, wdwh);
    transpose_h<0><<<dim3(16,16,1), 256>>>(wq, 0L, wqTh, 0L, DIM, DIM);

    // input transposes (fp16)
    transpose_h<0><<<dim3(128,16,BATCH), 256>>>(x, (long)DIM*MLEN, xTh, (long)MLEN*DIM, DIM, MLEN);
    ypad_zero_h<<<dim3(260,BATCH), 256>>>(yTh);
    transpose_h<1><<<dim3(128,16,BATCH), 256>>>(y, (long)DIM*MLEN, yTh, (long)YROWS*DIM, DIM, MLEN);

    // Wc2h[o2][r*512+c] = sum_o wdwh[r][o2][o] * wqTh[c][o]   (9 GEMMs, fp16 out)
    hgemm<0,1><<<dim3(4,4,9), 256, SMEMB>>>(
        wdwh, (long)DIM*DIM, wqTh, 0L, wc2h, 512L, KCONV, DIM, DIM);

    // kv = w_kv @ x  (fp32 out)
    hgemm<0,0><<<dim3(32,8,BATCH), 256, SMEMB>>>(
        wkvh, 0L, xTh, (long)MLEN*DIM, kv, (long)2*DIM*MLEN, MLEN, 2*DIM, DIM);

    // q = conv3x3 via implicit GEMM on padded transposed fp16 image
    hgemm<1,0><<<dim3(32,4,BATCH), 256, SMEMB>>>(
        wc2h, 0L, yTh, (long)YROWS*DIM, q, (long)DIM*MLEN, MLEN, DIM, KCONV);

    // vTh (fp16, n-major) from kv's v half
    transpose_h<0><<<dim3(128,16,BATCH), 256>>>(
        kv + (long)DIM*MLEN, (long)2*DIM*MLEN, vTh, (long)MLEN*DIM, DIM, MLEN);

    // attention
    attn_partial_kernel<<<dim3(8,HEADS,BATCH), 256>>>(q, kv, part, nsq);
    softmax_kernel<<<BATCH*HEADS*HD, 32>>>(part, nsq, temp, attn);
    w2_kernel_h<<<dim3(128,HEADS,BATCH), 256>>>(wout, attn, w2h);

    // out = W2 @ v
    hgemm<0,0><<<dim3(32,4,BATCH), 256, SMEMB>>>(
        w2h, (long)DIM*DIM, vTh, (long)MLEN*DIM, out, (long)DIM*MLEN, MLEN, DIM, DIM);
}

// round 7
// speedup vs baseline: 6.4410x; 1.1834x over previous
#include <cuda_runtime.h>
#include <cuda_fp16.h>
#include <math.h>
#include <stdint.h>

#define BATCH 4
#define DIM   512
#define MLEN  4096
#define HEADS 8
#define HD    64
#define KCONV 4608
#define YROWS 4356
#define SMEMB 61440   // 3 stages * (A 10240B + B 10240B)

// ---------------- static scratch ----------------
__device__ float  g_kv  [BATCH*DIM*MLEN];       // k only (fp32 [o][m])
__device__ float  g_q   [BATCH*DIM*MLEN];
__device__ float  g_part[BATCH*HEADS*8*HD*HD];
__device__ float  g_nsq [BATCH*HEADS*8*2*HD];
__device__ float  g_attn[BATCH*HEADS*HD*HD];
__device__ __half g_xTh [BATCH*MLEN*DIM];
__device__ __half g_yTh [BATCH*YROWS*DIM];
__device__ __half g_vTh [BATCH*MLEN*DIM];
__device__ __half g_wkvh[2*DIM*DIM];
__device__ __half g_wqTh[DIM*DIM];
__device__ __half g_wdwh[9*DIM*DIM];
__device__ __half g_wc2h[DIM*KCONV];
__device__ __half g_w2h [BATCH*DIM*DIM];

// ---------------- helpers ----------------
__device__ __forceinline__ void cpa16(uint32_t d, const void* s){
    asm volatile("cp.async.cg.shared.global [%0], [%1], 16;" :: "r"(d), "l"(s));
}
#define CP_COMMIT() asm volatile("cp.async.commit_group;")
#define CP_WAIT1()  asm volatile("cp.async.wait_group 1;")

__device__ __forceinline__ void mma16(float& c0, float& c1, float& c2, float& c3,
                                      uint32_t a0, uint32_t a1, uint32_t a2, uint32_t a3,
                                      uint32_t b0, uint32_t b1){
    asm volatile(
        "mma.sync.aligned.m16n8k16.row.col.f32.f16.f16.f32 "
        "{%0,%1,%2,%3}, {%4,%5,%6,%7}, {%8,%9}, {%0,%1,%2,%3};"
        : "+f"(c0), "+f"(c1), "+f"(c2), "+f"(c3)
        : "r"(a0), "r"(a1), "r"(a2), "r"(a3), "r"(b0), "r"(b1));
}
__device__ __forceinline__ void ldsm4(uint32_t& r0, uint32_t& r1, uint32_t& r2, uint32_t& r3,
                                      uint32_t a){
    asm volatile("ldmatrix.sync.aligned.m8n8.x4.shared.b16 {%0,%1,%2,%3}, [%4];"
        : "=r"(r0), "=r"(r1), "=r"(r2), "=r"(r3) : "r"(a));
}

// ---------------- fp16 tensor GEMM, cp.async 3-stage, ldmatrix frags --------
// C[z](MxN) = A[z](MxK fp16 row-major) * B[z]^T, B n-major [n][K] fp16
// (CONV: B = padded transposed image, k = r*512 + c).
// Block 128x128, BK=32, 8 warps, warp tile 64x32. Stage rows: 80B stride.
// OUTM: 0 = fp32 C, 1 = fp16 C, 2 = kv-special (bm<512 -> fp32 C; bm>=512 ->
//       fp16 transposed into VT via smem staging).
template<int CONV, int OUTM>
__global__ __launch_bounds__(256, 2)
void hgemm(const __half* __restrict__ A, long lA,
           const __half* __restrict__ B, long lB,
           void* __restrict__ Cv, long lC, int ldC,
           int M, int K, __half* __restrict__ VT)
{
    extern __shared__ __half sh[];
    const uint32_t smb = (uint32_t)__cvta_generic_to_shared(sh);
    A += (long)blockIdx.z * lA;
    B += (long)blockIdx.z * lB;
    const int bm = blockIdx.y * 128, bn = blockIdx.x * 128;
    const int tid = threadIdx.x, lane = tid & 31, warp = tid >> 5;
    const int wm = (warp >> 2) * 64, wn = (warp & 3) * 32;
    const int g = lane >> 2, t = lane & 3;

    const int lrow = tid >> 1;          // 0..127
    const int lco  = (tid & 1) * 16;    // halves 0 / 16

    int ph = 0, pw = 0;
    if (CONV) { const int n = bn + lrow; ph = n >> 6; pw = n & 63; }

    // ldmatrix source offsets (bytes within a stage)
    const uint32_t aOff = (uint32_t)((wm + (lane & 15)) * 80 + (lane >> 4) * 16);
    const uint32_t bOff = (uint32_t)((wn + (lane & 7) + ((lane >> 4) << 3)) * 80
                                     + ((lane >> 3) & 1) * 16);

    float acc[4][4][4];
#pragma unroll
    for (int i = 0; i < 4; i++)
#pragma unroll
        for (int j = 0; j < 4; j++)
#pragma unroll
            for (int r = 0; r < 4; r++) acc[i][j][r] = 0.f;

    const int T = K >> 5;

    auto load = [&](int s, int tt){
        const int k0 = tt << 5;
        const uint32_t sb = smb + (uint32_t)s * 20480u;
        const __half* asrc = A + (long)(bm + lrow) * K + k0 + lco;
        const uint32_t adst = sb + (uint32_t)lrow * 80u + (uint32_t)lco * 2u;
        cpa16(adst,       asrc);
        cpa16(adst + 16u, asrc + 8);
        const __half* bsrc;
        if (CONV) {
            const int r = k0 >> 9;
            const int dyr = r / 3, dxr = r - 3 * dyr;
            bsrc = B + ((long)((ph + dyr) * 66 + pw + dxr)) * DIM + (k0 & 511) + lco;
        } else {
            bsrc = B + (long)(bn + lrow) * K + k0 + lco;
        }
        const uint32_t bdst = sb + 10240u + (uint32_t)lrow * 80u + (uint32_t)lco * 2u;
        cpa16(bdst,       bsrc);
        cpa16(bdst + 16u, bsrc + 8);
    };

    load(0, 0); CP_COMMIT();
    load(1, 1); CP_COMMIT();

    for (int tt = 0; tt < T; tt++) {
        const int s = tt % 3;
        CP_WAIT1();
        __syncthreads();
        if (tt + 2 < T) load((tt + 2) % 3, tt + 2);
        CP_COMMIT();

        const uint32_t sb = smb + (uint32_t)s * 20480u;
#pragma unroll
        for (int ks = 0; ks < 2; ks++) {
            const uint32_t kb = (uint32_t)ks * 32u;
            uint32_t af[4][4], bf[2][4];
#pragma unroll
            for (int mi = 0; mi < 4; mi++)
                ldsm4(af[mi][0], af[mi][1], af[mi][2], af[mi][3],
                      sb + aOff + (uint32_t)mi * 1280u + kb);
            ldsm4(bf[0][0], bf[0][1], bf[0][2], bf[0][3], sb + 10240u + bOff + kb);
            ldsm4(bf[1][0], bf[1][1], bf[1][2], bf[1][3], sb + 10240u + bOff + 1280u + kb);
#pragma unroll
            for (int mi = 0; mi < 4; mi++)
#pragma unroll
                for (int ni = 0; ni < 4; ni++) {
                    const int p = ni >> 1, q2 = (ni & 1) * 2;
                    mma16(acc[mi][ni][0], acc[mi][ni][1], acc[mi][ni][2], acc[mi][ni][3],
                          af[mi][0], af[mi][1], af[mi][2], af[mi][3],
                          bf[p][q2], bf[p][q2 + 1]);
                }
        }
    }

    const bool vpath = (OUTM == 2) && (bm >= 512);
    if (OUTM == 1) {
        __half* C = (__half*)Cv + (long)blockIdx.z * lC;
#pragma unroll
        for (int mi = 0; mi < 4; mi++) {
            const int row0 = bm + wm + mi * 16 + g;
#pragma unroll
            for (int ni = 0; ni < 4; ni++) {
                const int col = bn + wn + ni * 8 + 2 * t;
                *(__half2*)(C + (long)row0 * ldC + col) =
                    __floats2half2_rn(acc[mi][ni][0], acc[mi][ni][1]);
                *(__half2*)(C + (long)(row0 + 8) * ldC + col) =
                    __floats2half2_rn(acc[mi][ni][2], acc[mi][ni][3]);
            }
        }
    } else if (!vpath) {
        float* C = (float*)Cv + (long)blockIdx.z * lC;
#pragma unroll
        for (int mi = 0; mi < 4; mi++) {
            const int row0 = bm + wm + mi * 16 + g;
#pragma unroll
            for (int ni = 0; ni < 4; ni++) {
                const int col = bn + wn + ni * 8 + 2 * t;
                *(float2*)(C + (long)row0 * ldC + col) =
                    make_float2(acc[mi][ni][0], acc[mi][ni][1]);
                *(float2*)(C + (long)(row0 + 8) * ldC + col) =
                    make_float2(acc[mi][ni][2], acc[mi][ni][3]);
            }
        }
    } else {
        // stage fp16 transposed tile in smem, then coalesced write to VT[m][o]
        __syncthreads();
#pragma unroll
        for (int mi = 0; mi < 4; mi++) {
            const int r0 = wm + mi * 16 + g;
#pragma unroll
            for (int ni = 0; ni < 4; ni++) {
                const int c0 = wn + ni * 8 + 2 * t;
                sh[(c0    ) * 136 + r0    ] = __float2half_rn(acc[mi][ni][0]);
                sh[(c0 + 1) * 136 + r0    ] = __float2half_rn(acc[mi][ni][1]);
                sh[(c0    ) * 136 + r0 + 8] = __float2half_rn(acc[mi][ni][2]);
                sh[(c0 + 1) * 136 + r0 + 8] = __float2half_rn(acc[mi][ni][3]);
            }
        }
        __syncthreads();
        __half* vt = VT + (long)blockIdx.z * MLEN * DIM;
        const int ml = tid >> 1, ho = (tid & 1) * 64;
        __half* dst = vt + (long)(bn + ml) * DIM + (bm - 512) + ho;
        const __half* srcp = sh + ml * 136 + ho;
#pragma unroll
        for (int i = 0; i < 8; i++)
            *(uint4*)(dst + i * 8) = *(const uint4*)(srcp + i * 8);
    }
}

// ---------------- prep / transpose kernels ----------------
__global__ void conv_h(const float* __restrict__ s, __half* __restrict__ d, int n){
    const int i = blockIdx.x * 256 + threadIdx.x;
    if (i < n) d[i] = __float2half_rn(s[i]);
}

template<int PADY>
__global__ void transpose_h(const float* __restrict__ S, long lS,
                            __half* __restrict__ D, long lD, int R, int C)
{
    __shared__ float tle[32][33];
    S += (long)blockIdx.z * lS;
    D += (long)blockIdx.z * lD;
    const int m0 = blockIdx.x * 32, c0 = blockIdx.y * 32;
    const int tx = threadIdx.x & 31, ty = threadIdx.x >> 5;
#pragma unroll
    for (int i = ty; i < 32; i += 8)
        tle[i][tx] = S[(long)(c0 + i) * C + m0 + tx];
    __syncthreads();
    const long prow = PADY ? (long)(m0 + 2 * (m0 >> 6) + 67) : (long)m0;
#pragma unroll
    for (int i = ty; i < 32; i += 8)
        D[(prow + i) * R + c0 + tx] = __float2half_rn(tle[tx][i]);
}

__global__ void ypad_zero_h(__half* __restrict__ yT)
{
    const int idx = blockIdx.x;
    int row;
    if (idx < 66) row = idx;
    else if (idx < 132) row = 65 * 66 + (idx - 66);
    else { const int i = idx - 132; row = (1 + (i >> 1)) * 66 + (i & 1) * 65; }
    uint32_t* p = (uint32_t*)(yT + ((long)blockIdx.y * YROWS + row) * DIM);
    p[threadIdx.x] = 0u;
}

__global__ void prep_wdw_h(const float* __restrict__ wdw, __half* __restrict__ wdwh)
{
    __shared__ float s[KCONV];
    const int o2 = blockIdx.x;
    const float* src = wdw + (long)o2 * KCONV;
    for (int i = threadIdx.x; i < KCONV; i += 256) s[i] = src[i];
    __syncthreads();
    for (int i = threadIdx.x; i < KCONV; i += 256) {
        const int r = i >> 9, o = i & 511;
        wdwh[((long)r * DIM + o2) * DIM + o] = __float2half_rn(s[o * 9 + r]);
    }
}

// ---------------- attention logits + fused sumsq ----------------
__global__ __launch_bounds__(256)
void attn_partial_kernel(const float* __restrict__ Q, const float* __restrict__ KV,
                         float* __restrict__ part, float* __restrict__ nsq)
{
    const int mc = blockIdx.x, h = blockIdx.y, b = blockIdx.z;
    const float* Qp = Q  + ((long)(b * DIM + h * HD)) * MLEN + mc * 512;
    const float* Kp = KV + ((long)(b * DIM + h * HD)) * MLEN + mc * 512;
    __shared__ float sq[32][64];
    __shared__ float sk[32][64];
    const int tid = threadIdx.x, row = tid >> 2, mg = (tid & 3) * 8;
    const int tx = tid & 15, ty = tid >> 4;
    float acc[4][4];
#pragma unroll
    for (int i = 0; i < 4; i++)
#pragma unroll
        for (int j = 0; j < 4; j++) acc[i][j] = 0.f;
    float ssq = 0.f, ssk = 0.f;
    for (int mt = 0; mt < 512; mt += 32) {
        float4 a0 = *(const float4*)(Qp + (long)row * MLEN + mt + mg);
        float4 a1 = *(const float4*)(Qp + (long)row * MLEN + mt + mg + 4);
        sq[mg+0][row]=a0.x; sq[mg+1][row]=a0.y; sq[mg+2][row]=a0.z; sq[mg+3][row]=a0.w;
        sq[mg+4][row]=a1.x; sq[mg+5][row]=a1.y; sq[mg+6][row]=a1.z; sq[mg+7][row]=a1.w;
        ssq += a0.x*a0.x+a0.y*a0.y+a0.z*a0.z+a0.w*a0.w + a1.x*a1.x+a1.y*a1.y+a1.z*a1.z+a1.w*a1.w;
        float4 b0 = *(const float4*)(Kp + (long)row * MLEN + mt + mg);
        float4 b1 = *(const float4*)(Kp + (long)row * MLEN + mt + mg + 4);
        sk[mg+0][row]=b0.x; sk[mg+1][row]=b0.y; sk[mg+2][row]=b0.z; sk[mg+3][row]=b0.w;
        sk[mg+4][row]=b1.x; sk[mg+5][row]=b1.y; sk[mg+6][row]=b1.z; sk[mg+7][row]=b1.w;
        ssk += b0.x*b0.x+b0.y*b0.y+b0.z*b0.z+b0.w*b0.w + b1.x*b1.x+b1.y*b1.y+b1.z*b1.z+b1.w*b1.w;
        __syncthreads();
#pragma unroll
        for (int mm = 0; mm < 32; mm++) {
            float ra[4], rb[4];
#pragma unroll
            for (int i = 0; i < 4; i++) ra[i] = sq[mm][ty*4+i];
#pragma unroll
            for (int j = 0; j < 4; j++) rb[j] = sk[mm][tx*4+j];
#pragma unroll
            for (int i = 0; i < 4; i++)
#pragma unroll
                for (int j = 0; j < 4; j++) acc[i][j] += ra[i]*rb[j];
        }
        __syncthreads();
    }
    ssq += __shfl_xor_sync(~0u, ssq, 1); ssq += __shfl_xor_sync(~0u, ssq, 2);
    ssk += __shfl_xor_sync(~0u, ssk, 1); ssk += __shfl_xor_sync(~0u, ssk, 2);
    if ((tid & 3) == 0) {
        const long nb = (((long)(b*HEADS + h))*8 + mc) * 2 * HD;
        nsq[nb + row] = ssq;
        nsq[nb + HD + row] = ssk;
    }
    float* pp = part + ((((long)(b*HEADS + h))*8 + mc)*HD + ty*4)*HD + tx*4;
#pragma unroll
    for (int i = 0; i < 4; i++)
#pragma unroll
        for (int j = 0; j < 4; j++) pp[i*HD + j] = acc[i][j];
}

__global__ void softmax_kernel(const float* __restrict__ part, const float* __restrict__ nsq,
                               const float* __restrict__ temp, float* __restrict__ attn)
{
    const int row = blockIdx.x;
    const int b = row >> 9, h = (row >> 6) & 7, c = row & 63;
    const int lane = threadIdx.x;
    const long nb = ((long)(b*HEADS + h)) * 8 * 2 * HD;
    float sqs = 0.f, sk0 = 0.f, sk1 = 0.f;
#pragma unroll
    for (int mc = 0; mc < 8; mc++) {
        sqs += nsq[nb + mc*2*HD + c];
        sk0 += nsq[nb + mc*2*HD + HD + lane];
        sk1 += nsq[nb + mc*2*HD + HD + lane + 32];
    }
    const float rq  = 1.f / fmaxf(sqrtf(sqs), 1e-12f);
    const float rk0 = 1.f / fmaxf(sqrtf(sk0), 1e-12f);
    const float rk1 = 1.f / fmaxf(sqrtf(sk1), 1e-12f);
    const float tq = rq * temp[h];
    const long base = (((long)(b*HEADS + h)) * 8) * (HD*HD) + c*HD;
    float s0 = 0.f, s1 = 0.f;
#pragma unroll
    for (int mc = 0; mc < 8; mc++) {
        s0 += part[base + (long)mc*(HD*HD) + lane];
        s1 += part[base + (long)mc*(HD*HD) + lane + 32];
    }
    float v0 = s0 * tq * rk0, v1 = s1 * tq * rk1;
    float mx = fmaxf(v0, v1);
#pragma unroll
    for (int o = 16; o; o >>= 1) mx = fmaxf(mx, __shfl_xor_sync(~0u, mx, o));
    const float e0 = expf(v0 - mx), e1 = expf(v1 - mx);
    float s = e0 + e1;
#pragma unroll
    for (int o = 16; o; o >>= 1) s += __shfl_xor_sync(~0u, s, o);
    const float inv = 1.f / s;
    float* ap = attn + (((long)(b*HEADS + h))*HD + c)*HD;
    ap[lane] = e0 * inv;
    ap[lane + 32] = e1 * inv;
}

// ---------------- W2h = half(w_out @ blockdiag(attn)) ----------------
__global__ void w2_kernel_h(const float* __restrict__ w_out, const float* __restrict__ attn,
                            __half* __restrict__ W2h)
{
    const int b = blockIdx.z, h = blockIdx.y;
    const int tid = threadIdx.x;
    __shared__ float sa[HD*HD];
    const float* ap = attn + ((long)(b*HEADS + h)) * HD * HD;
    for (int i = tid; i < HD*HD; i += 256) sa[i] = ap[i];
    __syncthreads();
    const int o = blockIdx.x * 4 + (tid >> 6);
    const int d = tid & 63;
    const float* wrow = w_out + (long)o * DIM + h * HD;
    float acc = 0.f;
#pragma unroll
    for (int c = 0; c < HD; c++) acc += wrow[c] * sa[c*HD + d];
    W2h[((long)b*DIM + o) * DIM + h*HD + d] = __float2half_rn(acc);
}

// ---------------- launcher ----------------
extern "C" void kernel_launch(void* const* d_in, const int* in_sizes, int n_in,
                              void* d_out, int out_size)
{
    const float* x    = (const float*)d_in[0];
    const float* y    = (const float*)d_in[1];
    const float* temp = (const float*)d_in[2];
    const float* wkv  = (const float*)d_in[3];
    const float* wq   = (const float*)d_in[4];
    const float* wdw  = (const float*)d_in[5];
    const float* wout = (const float*)d_in[6];
    float* out = (float*)d_out;

    float *kv, *q, *part, *nsq, *attn;
    __half *xTh, *yTh, *vTh, *wkvh, *wqTh, *wdwh, *wc2h, *w2h;
    cudaGetSymbolAddress((void**)&kv,   g_kv);
    cudaGetSymbolAddress((void**)&q,    g_q);
    cudaGetSymbolAddress((void**)&part, g_part);
    cudaGetSymbolAddress((void**)&nsq,  g_nsq);
    cudaGetSymbolAddress((void**)&attn, g_attn);
    cudaGetSymbolAddress((void**)&xTh,  g_xTh);
    cudaGetSymbolAddress((void**)&yTh,  g_yTh);
    cudaGetSymbolAddress((void**)&vTh,  g_vTh);
    cudaGetSymbolAddress((void**)&wkvh, g_wkvh);
    cudaGetSymbolAddress((void**)&wqTh, g_wqTh);
    cudaGetSymbolAddress((void**)&wdwh, g_wdwh);
    cudaGetSymbolAddress((void**)&wc2h, g_wc2h);
    cudaGetSymbolAddress((void**)&w2h,  g_w2h);

    cudaFuncSetAttribute(hgemm<0,0>, cudaFuncAttributeMaxDynamicSharedMemorySize, SMEMB);
    cudaFuncSetAttribute(hgemm<0,1>, cudaFuncAttributeMaxDynamicSharedMemorySize, SMEMB);
    cudaFuncSetAttribute(hgemm<0,2>, cudaFuncAttributeMaxDynamicSharedMemorySize, SMEMB);
    cudaFuncSetAttribute(hgemm<1,0>, cudaFuncAttributeMaxDynamicSharedMemorySize, SMEMB);

    // weight prep (fp16)
    conv_h<<<2048, 256>>>(wkv, wkvh, 2*DIM*DIM);
    prep_wdw_h<<<512, 256>>>(wdw, wdwh);
    transpose_h<0><<<dim3(16,16,1), 256>>>(wq, 0L, wqTh, 0L, DIM, DIM);

    // input transposes (fp16)
    transpose_h<0><<<dim3(128,16,BATCH), 256>>>(x, (long)DIM*MLEN, xTh, (long)MLEN*DIM, DIM, MLEN);
    ypad_zero_h<<<dim3(260,BATCH), 256>>>(yTh);
    transpose_h<1><<<dim3(128,16,BATCH), 256>>>(y, (long)DIM*MLEN, yTh, (long)YROWS*DIM, DIM, MLEN);

    // Wc2h[o2][r*512+c] = sum_o wdwh[r][o2][o] * wqTh[c][o]
    hgemm<0,1><<<dim3(4,4,9), 256, SMEMB>>>(
        wdwh, (long)DIM*DIM, wqTh, 0L, wc2h, 512L, KCONV, DIM, DIM, nullptr);

    // kv: k -> fp32 kv[o][m]; v -> fp16 vTh[m][o] (fused transpose epilogue)
    hgemm<0,2><<<dim3(32,8,BATCH), 256, SMEMB>>>(
        wkvh, 0L, xTh, (long)MLEN*DIM, kv, (long)DIM*MLEN, MLEN, 2*DIM, DIM, vTh);

    // q = conv3x3 via implicit GEMM on padded transposed fp16 image
    hgemm<1,0><<<dim3(32,4,BATCH), 256, SMEMB>>>(
        wc2h, 0L, yTh, (long)YROWS*DIM, q, (long)DIM*MLEN, MLEN, DIM, KCONV, nullptr);

    // attention
    attn_partial_kernel<<<dim3(8,HEADS,BATCH), 256>>>(q, kv, part, nsq);
    softmax_kernel<<<BATCH*HEADS*HD, 32>>>(part, nsq, temp, attn);
    w2_kernel_h<<<dim3(128,HEADS,BATCH), 256>>>(wout, attn, w2h);

    // out = W2 @ v
    hgemm<0,0><<<dim3(32,4,BATCH), 256, SMEMB>>>(
        w2h, (long)DIM*DIM, vTh, (long)MLEN*DIM, out, (long)DIM*MLEN, MLEN, DIM, DIM, nullptr);
}